// round 3
// baseline (speedup 1.0000x reference)
#include <cuda_runtime.h>
#include <math.h>

// ============================================================================
// ResidualGraph: B=4096, C=62, F_IN=256, OUT=BN=64, topK=10
//
// kernel 1 (proj): 4x GEMM [253952,256]@[256,64]
//     m=0: tanh(x@gate_w + gate_b)   -> x_mask
//     m=1: tanh(x@bnlin_w + bnlin_b) -> xa
//     m=2: x@rel_w1                  -> xr    (bias added later, after agg)
//     m=3: x@root_w1                 -> xroot
// kernel 2 (graph): per-batch CTA:
//     adj = softmax(xa@xa^T); keep top-10 (val,idx) per row
//     h = relu(sparse_agg(xr) + rel_b1 + xroot)
//     5x residual layers + final layer with w_mid[i]; out = h * x_mask
// ============================================================================

#define PSZ_ ((size_t)253952 * 64)     // 16,252,928 elems per projection

// scratch: [m][row][64], m in {mask, xa, xr, xroot}
__device__ float g_P[4 * 253952 * 64];

typedef unsigned long long ull;

// ---------------- f32x2 packed-FMA helpers (Blackwell FFMA2) ----------------
__device__ __forceinline__ ull pk(float x, float y) {
    ull r;
    asm("mov.b64 %0, {%1, %2};" : "=l"(r)
        : "r"(__float_as_uint(x)), "r"(__float_as_uint(y)));
    return r;
}
__device__ __forceinline__ float2 upk(ull p) {
    unsigned lo, hi;
    asm("mov.b64 {%0, %1}, %2;" : "=r"(lo), "=r"(hi) : "l"(p));
    return make_float2(__uint_as_float(lo), __uint_as_float(hi));
}
__device__ __forceinline__ ull f2(ull a, ull b, ull c) {
    ull d;
    asm("fma.rn.f32x2 %0, %1, %2, %3;" : "=l"(d) : "l"(a), "l"(b), "l"(c));
    return d;
}

// ============================================================================
// Kernel 1: projections. grid = (4 matrices, 3968 row-tiles), 256 threads.
// BM=64, BN=64, BK=16; 4x4 microtile as 2 row-pairs x 4 cols in f32x2.
// As stored transposed (row-pairs contiguous); Bs stored as duplicated u64
// pairs so the inner loop has ZERO pack movs: 3 LDS.128 + 8 FFMA2 per k.
// ============================================================================
__global__ __launch_bounds__(256) void proj_kernel(
    const float* __restrict__ X,
    const float* __restrict__ Wg, const float* __restrict__ Wb,
    const float* __restrict__ Wr, const float* __restrict__ Wo,
    const float* __restrict__ gb, const float* __restrict__ bb)
{
    __shared__ __align__(16) float As[16 * 64];   // As[k][row]
    __shared__ __align__(16) ull   Bs[16 * 64];   // Bs[k][col] duplicated (w,w)

    const int tid = threadIdx.x;
    const int m   = blockIdx.x;
    const float* W = (m == 0) ? Wg : (m == 1) ? Wb : (m == 2) ? Wr : Wo;

    const int ty = tid >> 4, tx = tid & 15;
    const size_t rowBase = (size_t)blockIdx.y * 64;

    const int ar = tid >> 2, aq = tid & 3;    // A staging: 64 rows x 4 k-quads
    const int bk = tid >> 4, bq = tid & 15;   // B staging: 16 k x 16 col-quads
    const float* Ag = X + (rowBase + ar) * 256 + aq * 4;
    const float* Bg = W + bk * 64 + bq * 4;

    ull acc[8];
#pragma unroll
    for (int i = 0; i < 8; i++) acc[i] = 0ull;

    float4 av = *(const float4*)Ag;
    float4 bv = *(const float4*)Bg;

    for (int k0 = 0; k0 < 256; k0 += 16) {
        __syncthreads();
        As[(aq * 4 + 0) * 64 + ar] = av.x;
        As[(aq * 4 + 1) * 64 + ar] = av.y;
        As[(aq * 4 + 2) * 64 + ar] = av.z;
        As[(aq * 4 + 3) * 64 + ar] = av.w;
        {
            ull* bd = Bs + bk * 64 + bq * 4;
            bd[0] = pk(bv.x, bv.x);
            bd[1] = pk(bv.y, bv.y);
            bd[2] = pk(bv.z, bv.z);
            bd[3] = pk(bv.w, bv.w);
        }
        __syncthreads();
        if (k0 + 16 < 256) {                      // prefetch next tile
            av = *(const float4*)(Ag + k0 + 16);
            bv = *(const float4*)(Bg + (k0 + 16) * 64);
        }
#pragma unroll
        for (int k = 0; k < 16; k++) {
            ulonglong2 a2  = *(const ulonglong2*)(As + k * 64 + ty * 4);
            ulonglong2 b2a = *(const ulonglong2*)(Bs + k * 64 + tx * 4);
            ulonglong2 b2b = *(const ulonglong2*)(Bs + k * 64 + tx * 4 + 2);
            acc[0] = f2(a2.x, b2a.x, acc[0]);
            acc[1] = f2(a2.x, b2a.y, acc[1]);
            acc[2] = f2(a2.x, b2b.x, acc[2]);
            acc[3] = f2(a2.x, b2b.y, acc[3]);
            acc[4] = f2(a2.y, b2a.x, acc[4]);
            acc[5] = f2(a2.y, b2a.y, acc[5]);
            acc[6] = f2(a2.y, b2b.x, acc[6]);
            acc[7] = f2(a2.y, b2b.y, acc[7]);
        }
    }

    float b0 = 0.f, b1 = 0.f, b2 = 0.f, b3 = 0.f;
    if (m == 0) {
        float4 t = *(const float4*)(gb + tx * 4);
        b0 = t.x; b1 = t.y; b2 = t.z; b3 = t.w;
    } else if (m == 1) {
        float4 t = *(const float4*)(bb + tx * 4);
        b0 = t.x; b1 = t.y; b2 = t.z; b3 = t.w;
    }

    float* Pm = g_P + (size_t)m * PSZ_ + rowBase * 64;
#pragma unroll
    for (int rp = 0; rp < 2; rp++) {
        float2 c0 = upk(acc[rp * 4 + 0]);
        float2 c1 = upk(acc[rp * 4 + 1]);
        float2 c2 = upk(acc[rp * 4 + 2]);
        float2 c3 = upk(acc[rp * 4 + 3]);
        float4 lo = make_float4(c0.x, c1.x, c2.x, c3.x);
        float4 hi = make_float4(c0.y, c1.y, c2.y, c3.y);
        if (m < 2) {
            lo.x = tanhf(lo.x + b0); lo.y = tanhf(lo.y + b1);
            lo.z = tanhf(lo.z + b2); lo.w = tanhf(lo.w + b3);
            hi.x = tanhf(hi.x + b0); hi.y = tanhf(hi.y + b1);
            hi.z = tanhf(hi.z + b2); hi.w = tanhf(hi.w + b3);
        }
        const int row0 = ty * 4 + rp * 2;
        *(float4*)(Pm + (size_t)row0 * 64 + tx * 4)       = lo;
        *(float4*)(Pm + (size_t)(row0 + 1) * 64 + tx * 4) = hi;
    }
}

// ============================================================================
// Kernel 2: per-batch graph phase. grid = 4096 CTAs x 256 threads.
//
// Thread map: rg = tid>>6 (0..3), col = tid&63. Thread owns rows rg+4t.
// Paired h layout: H(r,c) = ((r&3)*8 + (r>>3))*128 + c*2 + ((r>>2)&1)
//   -> LDS.128 at (pair,k) yields two f32x2 operands directly (zero packs).
// Static smem 37.2 KB: s_h 4096f (xa then h-paired), s_hr 4160f (xa^T pitch-65
// then hr/xr plain), s_tk 620 float2 top-k lists.
// ============================================================================
#define HIDX(r, c) ((((r) & 3) * 8 + ((r) >> 3)) * 128 + (c) * 2 + (((r) >> 2) & 1))

__global__ __launch_bounds__(256) void graph_kernel(
    const float* __restrict__ wrel_mid,
    const float* __restrict__ brel_mid,
    const float* __restrict__ wroot_mid,
    const float* __restrict__ relb1,
    float* __restrict__ out)
{
    __shared__ __align__(16) float  s_h[4096];
    __shared__ __align__(16) float  s_hr[4160];
    __shared__ __align__(16) float2 s_tk[620];

    const int tid = threadIdx.x;
    const int rg  = tid >> 6;
    const int col = tid & 63;
    const size_t base = (size_t)blockIdx.x * 3968;

    const float* P0 = g_P;                 // x_mask
    const float* P1 = g_P + PSZ_;          // xa
    const float* P2 = g_P + 2 * PSZ_;      // xr
    const float* P3 = g_P + 3 * PSZ_;      // xroot

    // ---- Phase A1: load xa plain (s_h) + transposed pitch-65 (s_hr) ----
    {
        const float* gxa = P1 + base;
        for (int i = tid; i < 3968; i += 256) {
            float v = gxa[i];
            s_h[i] = v;
            s_hr[(i & 63) * 65 + (i >> 6)] = v;
        }
    }
    __syncthreads();

    // ---- Phase A2: logits + softmax + top-10 (warp per row) ----
    {
        const int warp = tid >> 5, lane = tid & 31;
        const unsigned FULL = 0xFFFFFFFFu;
        for (int r = warp; r < 62; r += 8) {
            const float* xaR = s_h + r * 64;
            float acc0 = 0.f, acc1 = 0.f;
#pragma unroll
            for (int k = 0; k < 64; k++) {
                float a = xaR[k];
                acc0 = fmaf(a, s_hr[k * 65 + lane], acc0);
                acc1 = fmaf(a, s_hr[k * 65 + lane + 32], acc1);
            }
            const bool v1ok = (lane + 32) < 62;
            float l0 = acc0;
            float l1 = v1ok ? acc1 : -1e30f;
            float mx = fmaxf(l0, l1);
#pragma unroll
            for (int s = 16; s; s >>= 1) mx = fmaxf(mx, __shfl_xor_sync(FULL, mx, s));
            float e0 = __expf(l0 - mx);
            float e1 = v1ok ? __expf(l1 - mx) : 0.f;
            float sm = e0 + e1;
#pragma unroll
            for (int s = 16; s; s >>= 1) sm += __shfl_xor_sync(FULL, sm, s);
            const float inv = 1.f / sm;
            float p0 = e0 * inv;
            float p1 = e1 * inv;   // invalid lanes: exactly 0 (never wins vs >0)
            // 10 rounds: REDUX max on positive-float bits; ballots give the
            // exact lowest index on ties (matches jax top_k). Cleared -> 0.
            for (int t = 0; t < 10; t++) {
                unsigned u0 = __float_as_uint(p0);
                unsigned u1 = __float_as_uint(p1);
                unsigned mb = u0 > u1 ? u0 : u1;
                unsigned best = __reduce_max_sync(FULL, mb);
                unsigned m0 = __ballot_sync(FULL, u0 == best);
                unsigned m1 = __ballot_sync(FULL, u1 == best);
                int widx = m0 ? (__ffs(m0) - 1) : (__ffs(m1) - 1 + 32);
                if (lane == 0)
                    s_tk[r * 10 + t] =
                        make_float2(__uint_as_float(best), __int_as_float(widx));
                if (widx == lane)            p0 = 0.f;
                else if (widx == lane + 32)  p1 = 0.f;
            }
        }
    }
    __syncthreads();

    // ---- stage xr into s_hr (plain [62][64]); zero the 192-float tail so a
    //      degenerate top-k pick of row 62/63 reads exact zeros, never junk ----
    {
        const float4* gxr = (const float4*)(P2 + base);
        float4* dst = (float4*)s_hr;
        for (int i = tid; i < 992; i += 256) dst[i] = gxr[i];
        if (tid < 48)
            dst[992 + tid] = make_float4(0.f, 0.f, 0.f, 0.f);
    }
    __syncthreads();

    // ---- Layer 1: h = relu(agg(xr) + rel_b1 + xroot), write paired s_h ----
    {
        const float bi = relb1[col];
        const float* gxo = P3 + base;
        if (tid < 64) {  // zero pad rows 62/63 so their hr output is exactly 0
            s_h[HIDX(62, tid)] = 0.f;
            s_h[HIDX(63, tid)] = 0.f;
        }
#pragma unroll
        for (int t = 0; t < 16; t++) {
            const int r = rg + 4 * t;
            if (r < 62) {
                float acc = bi + gxo[r * 64 + col];
                const float2* tk = s_tk + r * 10;
#pragma unroll
                for (int u = 0; u < 10; u++) {
                    float2 e = tk[u];
                    acc = fmaf(e.x, s_hr[__float_as_int(e.y) * 64 + col], acc);
                }
                s_h[HIDX(r, col)] = fmaxf(acc, 0.f);
            }
        }
    }
    __syncthreads();

    // ---- Layers 2..7: GEMM (h@Wrel -> s_hr, h@Wroot -> regs) + sparse agg ----
    const int pb = rg * 8 * 128;   // paired base: H(rg+8s[+4], c) = pb+s*128+c*2[+1]
    for (int L = 0; L < 6; L++) {
        const float* Wr = wrel_mid  + L * 4096 + col;
        const float* Wo = wroot_mid + L * 4096 + col;

        ull aR[8], aO[8];
#pragma unroll
        for (int s = 0; s < 8; s++) { aR[s] = 0ull; aO[s] = 0ull; }

#pragma unroll 4
        for (int kq = 0; kq < 16; kq++) {
            const int k = kq * 4;
            const float w0 = Wr[(k + 0) * 64], w1 = Wr[(k + 1) * 64];
            const float w2 = Wr[(k + 2) * 64], w3 = Wr[(k + 3) * 64];
            const float v0 = Wo[(k + 0) * 64], v1 = Wo[(k + 1) * 64];
            const float v2 = Wo[(k + 2) * 64], v3 = Wo[(k + 3) * 64];
            const ull wr0 = pk(w0, w0), wr1 = pk(w1, w1);
            const ull wr2 = pk(w2, w2), wr3 = pk(w3, w3);
            const ull wo0 = pk(v0, v0), wo1 = pk(v1, v1);
            const ull wo2 = pk(v2, v2), wo3 = pk(v3, v3);
#pragma unroll
            for (int s = 0; s < 8; s++) {
                const float* hp = s_h + pb + s * 128 + k * 2;
                ulonglong2 hA = *(const ulonglong2*)(hp);      // k, k+1
                ulonglong2 hB = *(const ulonglong2*)(hp + 4);  // k+2, k+3
                aR[s] = f2(hA.x, wr0, aR[s]);
                aR[s] = f2(hA.y, wr1, aR[s]);
                aR[s] = f2(hB.x, wr2, aR[s]);
                aR[s] = f2(hB.y, wr3, aR[s]);
                aO[s] = f2(hA.x, wo0, aO[s]);
                aO[s] = f2(hA.y, wo1, aO[s]);
                aO[s] = f2(hB.x, wo2, aO[s]);
                aO[s] = f2(hB.y, wo3, aO[s]);
            }
        }

        // hr -> smem plain layout
#pragma unroll
        for (int s = 0; s < 8; s++) {
            float2 v = upk(aR[s]);
            const int r0 = rg + 8 * s;
            s_hr[r0 * 64 + col]       = v.x;
            s_hr[(r0 + 4) * 64 + col] = v.y;
        }
        __syncthreads();

        // sparse aggregation + bias + root + relu (+ residual / final output)
        const float brel = brel_mid[L * 64 + col];
        const bool last = (L == 5);
#pragma unroll
        for (int s = 0; s < 8; s++) {
            float2 hro = upk(aO[s]);
            const int r0 = rg + 8 * s;      // always < 62
            const int r1 = r0 + 4;
            {
                float acc = brel + hro.x;
                const float2* tk = s_tk + r0 * 10;
#pragma unroll
                for (int u = 0; u < 10; u++) {
                    float2 e = tk[u];
                    acc = fmaf(e.x, s_hr[__float_as_int(e.y) * 64 + col], acc);
                }
                float v = fmaxf(acc, 0.f);
                const int ha = pb + s * 128 + col * 2;
                if (last) out[base + r0 * 64 + col] = v * P0[base + r0 * 64 + col];
                else      s_h[ha] = s_h[ha] + v;
            }
            if (r1 < 62) {
                float acc = brel + hro.y;
                const float2* tk = s_tk + r1 * 10;
#pragma unroll
                for (int u = 0; u < 10; u++) {
                    float2 e = tk[u];
                    acc = fmaf(e.x, s_hr[__float_as_int(e.y) * 64 + col], acc);
                }
                float v = fmaxf(acc, 0.f);
                const int ha = pb + s * 128 + col * 2 + 1;
                if (last) out[base + r1 * 64 + col] = v * P0[base + r1 * 64 + col];
                else      s_h[ha] = s_h[ha] + v;
            }
        }
        __syncthreads();
    }
}

// ============================================================================
// launch
// ============================================================================
extern "C" void kernel_launch(void* const* d_in, const int* in_sizes, int n_in,
                              void* d_out, int out_size) {
    const float* x        = (const float*)d_in[0];
    const float* gate_w   = (const float*)d_in[1];
    const float* gate_b   = (const float*)d_in[2];
    const float* bnlin_w  = (const float*)d_in[3];
    const float* bnlin_b  = (const float*)d_in[4];
    const float* rel_w1   = (const float*)d_in[5];
    const float* rel_b1   = (const float*)d_in[6];
    const float* root_w1  = (const float*)d_in[7];
    const float* rel_w_m  = (const float*)d_in[8];
    const float* rel_b_m  = (const float*)d_in[9];
    const float* root_w_m = (const float*)d_in[10];
    float* out = (float*)d_out;

    proj_kernel<<<dim3(4, 3968), 256>>>(x, gate_w, bnlin_w, rel_w1, root_w1,
                                        gate_b, bnlin_b);
    graph_kernel<<<4096, 256>>>(rel_w_m, rel_b_m, root_w_m, rel_b1, out);
}

// round 4
// speedup vs baseline: 1.6969x; 1.6969x over previous
#include <cuda_runtime.h>
#include <math.h>

// ============================================================================
// ResidualGraph: B=4096, C=62, F_IN=256, OUT=BN=64, topK=10
//
// kernel 1 (proj): 4x GEMM [253952,256]@[256,64]
//   v2: 128x64 tile, warp owns 8-col block -> B loads are warp BROADCASTS
//       (0.56 B/MAC unique smem vs 3 B/MAC in v1) -> FMA-bound.
// kernel 2 (graph): per-batch CTA (softmax adj, top-10, 7 conv layers)
//   v2: <=124 regs (launch_bounds 256,2) -> 2 CTAs/SM; pipelined weight LDGs.
// ============================================================================

#define PSZ_ ((size_t)253952 * 64)     // elems per projection matrix

// scratch: [m][row][64], m in {mask, xa, xr, xroot}
__device__ float g_P[4 * 253952 * 64];

typedef unsigned long long ull;

// ---------------- f32x2 packed-FMA helpers (Blackwell FFMA2) ----------------
__device__ __forceinline__ ull pk(float x, float y) {
    ull r;
    asm("mov.b64 %0, {%1, %2};" : "=l"(r)
        : "r"(__float_as_uint(x)), "r"(__float_as_uint(y)));
    return r;
}
__device__ __forceinline__ float2 upk(ull p) {
    unsigned lo, hi;
    asm("mov.b64 {%0, %1}, %2;" : "=r"(lo), "=r"(hi) : "l"(p));
    return make_float2(__uint_as_float(lo), __uint_as_float(hi));
}
__device__ __forceinline__ ull f2(ull a, ull b, ull c) {
    ull d;
    asm("fma.rn.f32x2 %0, %1, %2, %3;" : "=l"(d) : "l"(a), "l"(b), "l"(c));
    return d;
}

// ============================================================================
// Kernel 1 v2: projections. grid = (4 matrices, 1984 row-tiles of 128), 256 thr.
// Tile 128 rows x 64 cols, BK=16. Lane owns rows 4l..4l+3 (2 native pairs) x
// the warp's 8-col block (warp w -> cols 8w..8w+7). B is stored duplicated
// (w,w) in smem; all 32 lanes of a warp read the SAME Bs address -> broadcast.
// Inner loop per k: 1 lane-varying LDS.128 (A) + 4 broadcast LDS.128 (B)
// + 16 FFMA2.  As pitch 132 kills staging bank conflicts.
// ============================================================================
__global__ __launch_bounds__(256, 2) void proj_kernel(
    const float* __restrict__ X,
    const float* __restrict__ Wg, const float* __restrict__ Wb,
    const float* __restrict__ Wr, const float* __restrict__ Wo,
    const float* __restrict__ gb, const float* __restrict__ bb)
{
    __shared__ __align__(16) float As[16 * 132];   // As[k][row], pitch 132
    __shared__ __align__(16) ull   Bs[16 * 64];    // Bs[k][col] duplicated (w,w)

    const int tid = threadIdx.x;
    const int m   = blockIdx.x;
    const float* W = (m == 0) ? Wg : (m == 1) ? Wb : (m == 2) ? Wr : Wo;

    const int lane = tid & 31, wrp = tid >> 5;
    const size_t rowBase = (size_t)blockIdx.y * 128;

    // staging roles
    const int ar = tid >> 1, aq0 = tid & 1;        // A: 128 rows x quads {aq0, aq0+2}
    const int bk = tid >> 4, bq = tid & 15;        // B: 16 k-rows x 16 col-quads
    const float* Ag = X + (rowBase + ar) * 256;
    const float* Bg = W + bk * 64 + bq * 4;

    ull acc[2][8];
#pragma unroll
    for (int rp = 0; rp < 2; rp++)
#pragma unroll
        for (int c = 0; c < 8; c++) acc[rp][c] = 0ull;

    float4 av0 = *(const float4*)(Ag + aq0 * 4);
    float4 av1 = *(const float4*)(Ag + (aq0 + 2) * 4);
    float4 bv  = *(const float4*)(Bg);

    for (int k0 = 0; k0 < 256; k0 += 16) {
        __syncthreads();
        As[(aq0 * 4 + 0) * 132 + ar] = av0.x;
        As[(aq0 * 4 + 1) * 132 + ar] = av0.y;
        As[(aq0 * 4 + 2) * 132 + ar] = av0.z;
        As[(aq0 * 4 + 3) * 132 + ar] = av0.w;
        As[((aq0 + 2) * 4 + 0) * 132 + ar] = av1.x;
        As[((aq0 + 2) * 4 + 1) * 132 + ar] = av1.y;
        As[((aq0 + 2) * 4 + 2) * 132 + ar] = av1.z;
        As[((aq0 + 2) * 4 + 3) * 132 + ar] = av1.w;
        {
            ull* bd = Bs + bk * 64 + bq * 4;
            bd[0] = pk(bv.x, bv.x);
            bd[1] = pk(bv.y, bv.y);
            bd[2] = pk(bv.z, bv.z);
            bd[3] = pk(bv.w, bv.w);
        }
        __syncthreads();
        if (k0 + 16 < 256) {                       // prefetch next tile
            av0 = *(const float4*)(Ag + k0 + 16 + aq0 * 4);
            av1 = *(const float4*)(Ag + k0 + 16 + (aq0 + 2) * 4);
            bv  = *(const float4*)(Bg + (k0 + 16) * 64);
        }
#pragma unroll
        for (int k = 0; k < 16; k++) {
            // A: rows 4l..4l+3 as 2 pairs (lane-varying)
            ulonglong2 a2 = *(const ulonglong2*)(As + k * 132 + lane * 4);
            // B: warp's 8 cols, duplicated -> 4 broadcast LDS.128
            const ull* bp = Bs + k * 64 + wrp * 8;
            ulonglong2 b01 = *(const ulonglong2*)(bp);
            ulonglong2 b23 = *(const ulonglong2*)(bp + 2);
            ulonglong2 b45 = *(const ulonglong2*)(bp + 4);
            ulonglong2 b67 = *(const ulonglong2*)(bp + 6);
            acc[0][0] = f2(a2.x, b01.x, acc[0][0]);
            acc[0][1] = f2(a2.x, b01.y, acc[0][1]);
            acc[0][2] = f2(a2.x, b23.x, acc[0][2]);
            acc[0][3] = f2(a2.x, b23.y, acc[0][3]);
            acc[0][4] = f2(a2.x, b45.x, acc[0][4]);
            acc[0][5] = f2(a2.x, b45.y, acc[0][5]);
            acc[0][6] = f2(a2.x, b67.x, acc[0][6]);
            acc[0][7] = f2(a2.x, b67.y, acc[0][7]);
            acc[1][0] = f2(a2.y, b01.x, acc[1][0]);
            acc[1][1] = f2(a2.y, b01.y, acc[1][1]);
            acc[1][2] = f2(a2.y, b23.x, acc[1][2]);
            acc[1][3] = f2(a2.y, b23.y, acc[1][3]);
            acc[1][4] = f2(a2.y, b45.x, acc[1][4]);
            acc[1][5] = f2(a2.y, b45.y, acc[1][5]);
            acc[1][6] = f2(a2.y, b67.x, acc[1][6]);
            acc[1][7] = f2(a2.y, b67.y, acc[1][7]);
        }
    }

    // bias for the warp's 8 cols
    float bia[8];
#pragma unroll
    for (int c = 0; c < 8; c++) bia[c] = 0.f;
    if (m == 0) {
        float4 t0 = *(const float4*)(gb + wrp * 8);
        float4 t1 = *(const float4*)(gb + wrp * 8 + 4);
        bia[0] = t0.x; bia[1] = t0.y; bia[2] = t0.z; bia[3] = t0.w;
        bia[4] = t1.x; bia[5] = t1.y; bia[6] = t1.z; bia[7] = t1.w;
    } else if (m == 1) {
        float4 t0 = *(const float4*)(bb + wrp * 8);
        float4 t1 = *(const float4*)(bb + wrp * 8 + 4);
        bia[0] = t0.x; bia[1] = t0.y; bia[2] = t0.z; bia[3] = t0.w;
        bia[4] = t1.x; bia[5] = t1.y; bia[6] = t1.z; bia[7] = t1.w;
    }

    float* Pm = g_P + (size_t)m * PSZ_ + rowBase * 64;
#pragma unroll
    for (int rp = 0; rp < 2; rp++) {
        float2 c0 = upk(acc[rp][0]), c1 = upk(acc[rp][1]);
        float2 c2 = upk(acc[rp][2]), c3 = upk(acc[rp][3]);
        float2 c4 = upk(acc[rp][4]), c5 = upk(acc[rp][5]);
        float2 c6 = upk(acc[rp][6]), c7 = upk(acc[rp][7]);
#pragma unroll
        for (int j = 0; j < 2; j++) {
            const int row = lane * 4 + rp * 2 + j;
            float4 lo, hi;
            lo.x = j ? c0.y : c0.x;  lo.y = j ? c1.y : c1.x;
            lo.z = j ? c2.y : c2.x;  lo.w = j ? c3.y : c3.x;
            hi.x = j ? c4.y : c4.x;  hi.y = j ? c5.y : c5.x;
            hi.z = j ? c6.y : c6.x;  hi.w = j ? c7.y : c7.x;
            if (m < 2) {
                lo.x = tanhf(lo.x + bia[0]); lo.y = tanhf(lo.y + bia[1]);
                lo.z = tanhf(lo.z + bia[2]); lo.w = tanhf(lo.w + bia[3]);
                hi.x = tanhf(hi.x + bia[4]); hi.y = tanhf(hi.y + bia[5]);
                hi.z = tanhf(hi.z + bia[6]); hi.w = tanhf(hi.w + bia[7]);
            }
            float* dst = Pm + (size_t)row * 64 + wrp * 8;   // 32B sector-aligned
            *(float4*)(dst)     = lo;
            *(float4*)(dst + 4) = hi;
        }
    }
}

// ============================================================================
// Kernel 2 v2: per-batch graph phase. grid = 4096 CTAs x 256 threads.
// Same structure as v1 (phase A, layer 1, agg all retained verbatim), but the
// layer GEMM is re-pipelined: 2 k's per step, 4 LDG prefetched one step ahead,
// no big unroll -> regs fit 2 CTAs/SM (launch_bounds 256,2).
// Paired h layout: H(r,c) = ((r&3)*8 + (r>>3))*128 + c*2 + ((r>>2)&1)
// ============================================================================
#define HIDX(r, c) ((((r) & 3) * 8 + ((r) >> 3)) * 128 + (c) * 2 + (((r) >> 2) & 1))

__global__ __launch_bounds__(256, 2) void graph_kernel(
    const float* __restrict__ wrel_mid,
    const float* __restrict__ brel_mid,
    const float* __restrict__ wroot_mid,
    const float* __restrict__ relb1,
    float* __restrict__ out)
{
    __shared__ __align__(16) float  s_h[4096];
    __shared__ __align__(16) float  s_hr[4160];
    __shared__ __align__(16) float2 s_tk[620];

    const int tid = threadIdx.x;
    const int rg  = tid >> 6;
    const int col = tid & 63;
    const size_t base = (size_t)blockIdx.x * 3968;

    const float* P0 = g_P;                 // x_mask
    const float* P1 = g_P + PSZ_;          // xa
    const float* P2 = g_P + 2 * PSZ_;      // xr
    const float* P3 = g_P + 3 * PSZ_;      // xroot

    // ---- Phase A1: load xa plain (s_h) + transposed pitch-65 (s_hr) ----
    {
        const float* gxa = P1 + base;
        for (int i = tid; i < 3968; i += 256) {
            float v = gxa[i];
            s_h[i] = v;
            s_hr[(i & 63) * 65 + (i >> 6)] = v;
        }
    }
    __syncthreads();

    // ---- Phase A2: logits + softmax + top-10 (warp per row) ----
    {
        const int warp = tid >> 5, lane = tid & 31;
        const unsigned FULL = 0xFFFFFFFFu;
        for (int r = warp; r < 62; r += 8) {
            const float* xaR = s_h + r * 64;
            float acc0 = 0.f, acc1 = 0.f;
#pragma unroll
            for (int k = 0; k < 64; k++) {
                float a = xaR[k];
                acc0 = fmaf(a, s_hr[k * 65 + lane], acc0);
                acc1 = fmaf(a, s_hr[k * 65 + lane + 32], acc1);
            }
            const bool v1ok = (lane + 32) < 62;
            float l0 = acc0;
            float l1 = v1ok ? acc1 : -1e30f;
            float mx = fmaxf(l0, l1);
#pragma unroll
            for (int s = 16; s; s >>= 1) mx = fmaxf(mx, __shfl_xor_sync(FULL, mx, s));
            float e0 = __expf(l0 - mx);
            float e1 = v1ok ? __expf(l1 - mx) : 0.f;
            float sm = e0 + e1;
#pragma unroll
            for (int s = 16; s; s >>= 1) sm += __shfl_xor_sync(FULL, sm, s);
            const float inv = 1.f / sm;
            float p0 = e0 * inv;
            float p1 = e1 * inv;   // invalid lanes: exactly 0 (never wins vs >0)
            for (int t = 0; t < 10; t++) {
                unsigned u0 = __float_as_uint(p0);
                unsigned u1 = __float_as_uint(p1);
                unsigned mb = u0 > u1 ? u0 : u1;
                unsigned best = __reduce_max_sync(FULL, mb);
                unsigned m0 = __ballot_sync(FULL, u0 == best);
                unsigned m1 = __ballot_sync(FULL, u1 == best);
                int widx = m0 ? (__ffs(m0) - 1) : (__ffs(m1) - 1 + 32);
                if (lane == 0)
                    s_tk[r * 10 + t] =
                        make_float2(__uint_as_float(best), __int_as_float(widx));
                if (widx == lane)            p0 = 0.f;
                else if (widx == lane + 32)  p1 = 0.f;
            }
        }
    }
    __syncthreads();

    // ---- stage xr into s_hr (plain [62][64]); zero the tail so degenerate
    //      top-k picks of row 62/63 read exact zeros, never junk ----
    {
        const float4* gxr = (const float4*)(P2 + base);
        float4* dst = (float4*)s_hr;
        for (int i = tid; i < 992; i += 256) dst[i] = gxr[i];
        if (tid < 48)
            dst[992 + tid] = make_float4(0.f, 0.f, 0.f, 0.f);
    }
    __syncthreads();

    // ---- Layer 1: h = relu(agg(xr) + rel_b1 + xroot), write paired s_h ----
    {
        const float bi = relb1[col];
        const float* gxo = P3 + base;
        if (tid < 64) {  // zero pad rows 62/63 so their GEMM contribution is 0
            s_h[HIDX(62, tid)] = 0.f;
            s_h[HIDX(63, tid)] = 0.f;
        }
#pragma unroll
        for (int t = 0; t < 16; t++) {
            const int r = rg + 4 * t;
            if (r < 62) {
                float acc = bi + gxo[r * 64 + col];
                const float2* tk = s_tk + r * 10;
#pragma unroll
                for (int u = 0; u < 10; u++) {
                    float2 e = tk[u];
                    acc = fmaf(e.x, s_hr[__float_as_int(e.y) * 64 + col], acc);
                }
                s_h[HIDX(r, col)] = fmaxf(acc, 0.f);
            }
        }
    }
    __syncthreads();

    // ---- Layers 2..7: GEMM (h@Wrel -> s_hr, h@Wroot -> regs) + sparse agg ----
    const int pb = rg * 8 * 128;   // paired base: rows (rg+8s, rg+8s+4)
    for (int L = 0; L < 6; L++) {
        const float* Wr = wrel_mid  + L * 4096 + col;
        const float* Wo = wroot_mid + L * 4096 + col;

        ull aR[8], aO[8];
#pragma unroll
        for (int s = 0; s < 8; s++) { aR[s] = 0ull; aO[s] = 0ull; }

        // software-pipelined weight LDGs, 2 k's per step
        float w0n = Wr[0],  w1n = Wr[64];
        float v0n = Wo[0],  v1n = Wo[64];
#pragma unroll 2
        for (int kk = 0; kk < 32; kk++) {
            const float w0 = w0n, w1 = w1n, v0 = v0n, v1 = v1n;
            const int kn = (kk < 31) ? (2 * kk + 2) : 62;  // last: harmless reload
            w0n = Wr[kn * 64];       w1n = Wr[(kn + 1) * 64];
            v0n = Wo[kn * 64];       v1n = Wo[(kn + 1) * 64];
            const ull wr0 = pk(w0, w0), wr1 = pk(w1, w1);
            const ull wo0 = pk(v0, v0), wo1 = pk(v1, v1);
            const float* hp = s_h + pb + kk * 4;
#pragma unroll
            for (int s = 0; s < 8; s++) {
                ulonglong2 hA = *(const ulonglong2*)(hp + s * 128);  // broadcast
                aR[s] = f2(hA.x, wr0, aR[s]);
                aR[s] = f2(hA.y, wr1, aR[s]);
                aO[s] = f2(hA.x, wo0, aO[s]);
                aO[s] = f2(hA.y, wo1, aO[s]);
            }
        }

        // hr -> smem plain layout
#pragma unroll
        for (int s = 0; s < 8; s++) {
            float2 v = upk(aR[s]);
            const int r0 = rg + 8 * s;
            s_hr[r0 * 64 + col]       = v.x;
            s_hr[(r0 + 4) * 64 + col] = v.y;
        }
        __syncthreads();

        // sparse aggregation + bias + root + relu (+ residual / final output)
        const float brel = brel_mid[L * 64 + col];
        const bool last = (L == 5);
#pragma unroll
        for (int s = 0; s < 8; s++) {
            float2 hro = upk(aO[s]);
            const int r0 = rg + 8 * s;      // always < 62
            const int r1 = r0 + 4;
            {
                float acc = brel + hro.x;
                const float2* tk = s_tk + r0 * 10;
#pragma unroll
                for (int u = 0; u < 10; u++) {
                    float2 e = tk[u];
                    acc = fmaf(e.x, s_hr[__float_as_int(e.y) * 64 + col], acc);
                }
                float v = fmaxf(acc, 0.f);
                const int ha = pb + s * 128 + col * 2;
                if (last) out[base + r0 * 64 + col] = v * P0[base + r0 * 64 + col];
                else      s_h[ha] = s_h[ha] + v;
            }
            if (r1 < 62) {
                float acc = brel + hro.y;
                const float2* tk = s_tk + r1 * 10;
#pragma unroll
                for (int u = 0; u < 10; u++) {
                    float2 e = tk[u];
                    acc = fmaf(e.x, s_hr[__float_as_int(e.y) * 64 + col], acc);
                }
                float v = fmaxf(acc, 0.f);
                const int ha = pb + s * 128 + col * 2 + 1;
                if (last) out[base + r1 * 64 + col] = v * P0[base + r1 * 64 + col];
                else      s_h[ha] = s_h[ha] + v;
            }
        }
        __syncthreads();
    }
}

// ============================================================================
// launch
// ============================================================================
extern "C" void kernel_launch(void* const* d_in, const int* in_sizes, int n_in,
                              void* d_out, int out_size) {
    const float* x        = (const float*)d_in[0];
    const float* gate_w   = (const float*)d_in[1];
    const float* gate_b   = (const float*)d_in[2];
    const float* bnlin_w  = (const float*)d_in[3];
    const float* bnlin_b  = (const float*)d_in[4];
    const float* rel_w1   = (const float*)d_in[5];
    const float* rel_b1   = (const float*)d_in[6];
    const float* root_w1  = (const float*)d_in[7];
    const float* rel_w_m  = (const float*)d_in[8];
    const float* rel_b_m  = (const float*)d_in[9];
    const float* root_w_m = (const float*)d_in[10];
    float* out = (float*)d_out;

    proj_kernel<<<dim3(4, 1984), 256>>>(x, gate_w, bnlin_w, rel_w1, root_w1,
                                        gate_b, bnlin_b);
    graph_kernel<<<4096, 256>>>(rel_w_m, rel_b_m, root_w_m, rel_b1, out);
}

// round 7
// speedup vs baseline: 1.8033x; 1.0627x over previous
#include <cuda_runtime.h>
#include <math.h>

// ============================================================================
// ResidualGraph: B=4096, C=62, F_IN=256, OUT=BN=64, topK=10
//
// kernel 0 (prep): duplicate mid weights into (w,w) u64 pairs, k-parity
//                  interleaved -> main loop loads LDG.128, zero packs.
// kernel 1 (proj): 4x GEMM [253952,256]@[256,64]  (128x64 tile, broadcast B)
// kernel 2 (graph): per-batch CTA (softmax adj, top-10, 7 conv layers)
// v3: launch_bounds(256,3) on proj+graph -> 24 warps/SM (was 16).
// ============================================================================

#define PSZ_ ((size_t)253952 * 64)     // elems per projection matrix

// scratch: [m][row][64], m in {mask, xa, xr, xroot}
__device__ float g_P[4 * 253952 * 64];

typedef unsigned long long ull;

// duplicated mid weights: ull index = ((Lm*32 + kk)*64 + col)*2 + (k&1),
// Lm = L*2 + mat (mat 0 = rel, 1 = root), k = 2*kk + parity.
// __align__(16): read through ulonglong2* (LDG.128 needs 16B alignment).
__device__ __align__(16) ull g_Wdup[12 * 32 * 64 * 2];

// ---------------- f32x2 packed-FMA helpers (Blackwell FFMA2) ----------------
__device__ __forceinline__ ull pk(float x, float y) {
    ull r;
    asm("mov.b64 %0, {%1, %2};" : "=l"(r)
        : "r"(__float_as_uint(x)), "r"(__float_as_uint(y)));
    return r;
}
__device__ __forceinline__ float2 upk(ull p) {
    unsigned lo, hi;
    asm("mov.b64 {%0, %1}, %2;" : "=r"(lo), "=r"(hi) : "l"(p));
    return make_float2(__uint_as_float(lo), __uint_as_float(hi));
}
__device__ __forceinline__ ull f2(ull a, ull b, ull c) {
    ull d;
    asm("fma.rn.f32x2 %0, %1, %2, %3;" : "=l"(d) : "l"(a), "l"(b), "l"(c));
    return d;
}

// ============================================================================
// Kernel 0: weight duplication. 49152 elements total (exactly 192*256 thr).
// ============================================================================
__global__ void prep_kernel(const float* __restrict__ wrel_mid,
                            const float* __restrict__ wroot_mid)
{
    const int i = blockIdx.x * 256 + threadIdx.x;   // 0 .. 49151
    const int Lm  = i >> 12;          // 0..11
    const int rem = i & 4095;
    const int k   = rem >> 6;         // 0..63
    const int col = rem & 63;
    const int L   = Lm >> 1;
    const float w = (Lm & 1) ? wroot_mid[L * 4096 + k * 64 + col]
                             : wrel_mid [L * 4096 + k * 64 + col];
    g_Wdup[(((size_t)Lm * 32 + (k >> 1)) * 64 + col) * 2 + (k & 1)] = pk(w, w);
}

// ============================================================================
// Kernel 1: projections. grid = (4 matrices, 1984 row-tiles of 128), 256 thr.
// Tile 128 rows x 64 cols, BK=16. Lane owns rows 4l..4l+3 (2 native pairs) x
// the warp's 8-col block; B duplicated in smem -> warp-broadcast LDS.
// Inner loop per k: 1 lane-varying LDS.128 + 4 broadcast LDS.128 + 16 FFMA2.
// ============================================================================
__global__ __launch_bounds__(256, 3) void proj_kernel(
    const float* __restrict__ X,
    const float* __restrict__ Wg, const float* __restrict__ Wb,
    const float* __restrict__ Wr, const float* __restrict__ Wo,
    const float* __restrict__ gb, const float* __restrict__ bb)
{
    __shared__ __align__(16) float As[16 * 132];   // As[k][row], pitch 132
    __shared__ __align__(16) ull   Bs[16 * 64];    // Bs[k][col] duplicated (w,w)

    const int tid = threadIdx.x;
    const int m   = blockIdx.x;
    const float* W = (m == 0) ? Wg : (m == 1) ? Wb : (m == 2) ? Wr : Wo;

    const int lane = tid & 31, wrp = tid >> 5;
    const size_t rowBase = (size_t)blockIdx.y * 128;

    const int ar = tid >> 1, aq0 = tid & 1;        // A: 128 rows x quads {aq0, aq0+2}
    const int bk = tid >> 4, bq = tid & 15;        // B: 16 k-rows x 16 col-quads
    const float* Ag = X + (rowBase + ar) * 256;
    const float* Bg = W + bk * 64 + bq * 4;

    ull acc[2][8];
#pragma unroll
    for (int rp = 0; rp < 2; rp++)
#pragma unroll
        for (int c = 0; c < 8; c++) acc[rp][c] = 0ull;

    float4 av0 = *(const float4*)(Ag + aq0 * 4);
    float4 av1 = *(const float4*)(Ag + (aq0 + 2) * 4);
    float4 bv  = *(const float4*)(Bg);

    for (int k0 = 0; k0 < 256; k0 += 16) {
        __syncthreads();
        As[(aq0 * 4 + 0) * 132 + ar] = av0.x;
        As[(aq0 * 4 + 1) * 132 + ar] = av0.y;
        As[(aq0 * 4 + 2) * 132 + ar] = av0.z;
        As[(aq0 * 4 + 3) * 132 + ar] = av0.w;
        As[((aq0 + 2) * 4 + 0) * 132 + ar] = av1.x;
        As[((aq0 + 2) * 4 + 1) * 132 + ar] = av1.y;
        As[((aq0 + 2) * 4 + 2) * 132 + ar] = av1.z;
        As[((aq0 + 2) * 4 + 3) * 132 + ar] = av1.w;
        {
            ull* bd = Bs + bk * 64 + bq * 4;
            bd[0] = pk(bv.x, bv.x);
            bd[1] = pk(bv.y, bv.y);
            bd[2] = pk(bv.z, bv.z);
            bd[3] = pk(bv.w, bv.w);
        }
        __syncthreads();
        if (k0 + 16 < 256) {                       // prefetch next tile
            av0 = *(const float4*)(Ag + k0 + 16 + aq0 * 4);
            av1 = *(const float4*)(Ag + k0 + 16 + (aq0 + 2) * 4);
            bv  = *(const float4*)(Bg + (k0 + 16) * 64);
        }
#pragma unroll
        for (int k = 0; k < 16; k++) {
            ulonglong2 a2 = *(const ulonglong2*)(As + k * 132 + lane * 4);
            const ull* bp = Bs + k * 64 + wrp * 8;
            ulonglong2 b01 = *(const ulonglong2*)(bp);
            ulonglong2 b23 = *(const ulonglong2*)(bp + 2);
            ulonglong2 b45 = *(const ulonglong2*)(bp + 4);
            ulonglong2 b67 = *(const ulonglong2*)(bp + 6);
            acc[0][0] = f2(a2.x, b01.x, acc[0][0]);
            acc[0][1] = f2(a2.x, b01.y, acc[0][1]);
            acc[0][2] = f2(a2.x, b23.x, acc[0][2]);
            acc[0][3] = f2(a2.x, b23.y, acc[0][3]);
            acc[0][4] = f2(a2.x, b45.x, acc[0][4]);
            acc[0][5] = f2(a2.x, b45.y, acc[0][5]);
            acc[0][6] = f2(a2.x, b67.x, acc[0][6]);
            acc[0][7] = f2(a2.x, b67.y, acc[0][7]);
            acc[1][0] = f2(a2.y, b01.x, acc[1][0]);
            acc[1][1] = f2(a2.y, b01.y, acc[1][1]);
            acc[1][2] = f2(a2.y, b23.x, acc[1][2]);
            acc[1][3] = f2(a2.y, b23.y, acc[1][3]);
            acc[1][4] = f2(a2.y, b45.x, acc[1][4]);
            acc[1][5] = f2(a2.y, b45.y, acc[1][5]);
            acc[1][6] = f2(a2.y, b67.x, acc[1][6]);
            acc[1][7] = f2(a2.y, b67.y, acc[1][7]);
        }
    }

    float bia[8];
#pragma unroll
    for (int c = 0; c < 8; c++) bia[c] = 0.f;
    if (m == 0) {
        float4 t0 = *(const float4*)(gb + wrp * 8);
        float4 t1 = *(const float4*)(gb + wrp * 8 + 4);
        bia[0] = t0.x; bia[1] = t0.y; bia[2] = t0.z; bia[3] = t0.w;
        bia[4] = t1.x; bia[5] = t1.y; bia[6] = t1.z; bia[7] = t1.w;
    } else if (m == 1) {
        float4 t0 = *(const float4*)(bb + wrp * 8);
        float4 t1 = *(const float4*)(bb + wrp * 8 + 4);
        bia[0] = t0.x; bia[1] = t0.y; bia[2] = t0.z; bia[3] = t0.w;
        bia[4] = t1.x; bia[5] = t1.y; bia[6] = t1.z; bia[7] = t1.w;
    }

    float* Pm = g_P + (size_t)m * PSZ_ + rowBase * 64;
#pragma unroll
    for (int rp = 0; rp < 2; rp++) {
        float2 c0 = upk(acc[rp][0]), c1 = upk(acc[rp][1]);
        float2 c2 = upk(acc[rp][2]), c3 = upk(acc[rp][3]);
        float2 c4 = upk(acc[rp][4]), c5 = upk(acc[rp][5]);
        float2 c6 = upk(acc[rp][6]), c7 = upk(acc[rp][7]);
#pragma unroll
        for (int j = 0; j < 2; j++) {
            const int row = lane * 4 + rp * 2 + j;
            float4 lo, hi;
            lo.x = j ? c0.y : c0.x;  lo.y = j ? c1.y : c1.x;
            lo.z = j ? c2.y : c2.x;  lo.w = j ? c3.y : c3.x;
            hi.x = j ? c4.y : c4.x;  hi.y = j ? c5.y : c5.x;
            hi.z = j ? c6.y : c6.x;  hi.w = j ? c7.y : c7.x;
            if (m < 2) {
                lo.x = tanhf(lo.x + bia[0]); lo.y = tanhf(lo.y + bia[1]);
                lo.z = tanhf(lo.z + bia[2]); lo.w = tanhf(lo.w + bia[3]);
                hi.x = tanhf(hi.x + bia[4]); hi.y = tanhf(hi.y + bia[5]);
                hi.z = tanhf(hi.z + bia[6]); hi.w = tanhf(hi.w + bia[7]);
            }
            float* dst = Pm + (size_t)row * 64 + wrp * 8;
            *(float4*)(dst)     = lo;
            *(float4*)(dst + 4) = hi;
        }
    }
}

// ============================================================================
// Kernel 2: per-batch graph phase. grid = 4096 CTAs x 256 threads.
// Paired h layout: H(r,c) = ((r&3)*8 + (r>>3))*128 + c*2 + ((r>>2)&1)
// Main loop per kk (2 k's): 2 LDG.128 (dup weights) + 8 broadcast LDS.128
// + 32 FFMA2, zero packs.  launch_bounds(256,3) -> 3 CTAs/SM.
// ============================================================================
#define HIDX(r, c) ((((r) & 3) * 8 + ((r) >> 3)) * 128 + (c) * 2 + (((r) >> 2) & 1))

__global__ __launch_bounds__(256, 3) void graph_kernel(
    const float* __restrict__ brel_mid,
    const float* __restrict__ relb1,
    float* __restrict__ out)
{
    __shared__ __align__(16) float  s_h[4096];
    __shared__ __align__(16) float  s_hr[4160];
    __shared__ __align__(16) float2 s_tk[620];

    const int tid = threadIdx.x;
    const int rg  = tid >> 6;
    const int col = tid & 63;
    const size_t base = (size_t)blockIdx.x * 3968;

    const float* P0 = g_P;                 // x_mask
    const float* P1 = g_P + PSZ_;          // xa
    const float* P2 = g_P + 2 * PSZ_;      // xr
    const float* P3 = g_P + 3 * PSZ_;      // xroot

    // ---- Phase A1: load xa plain (s_h) + transposed pitch-65 (s_hr) ----
    {
        const float* gxa = P1 + base;
        for (int i = tid; i < 3968; i += 256) {
            float v = gxa[i];
            s_h[i] = v;
            s_hr[(i & 63) * 65 + (i >> 6)] = v;
        }
    }
    __syncthreads();

    // ---- Phase A2: logits + softmax + top-10 (warp per row) ----
    {
        const int warp = tid >> 5, lane = tid & 31;
        const unsigned FULL = 0xFFFFFFFFu;
        for (int r = warp; r < 62; r += 8) {
            const float* xaR = s_h + r * 64;
            float acc0 = 0.f, acc1 = 0.f;
#pragma unroll
            for (int k = 0; k < 64; k++) {
                float a = xaR[k];
                acc0 = fmaf(a, s_hr[k * 65 + lane], acc0);
                acc1 = fmaf(a, s_hr[k * 65 + lane + 32], acc1);
            }
            const bool v1ok = (lane + 32) < 62;
            float l0 = acc0;
            float l1 = v1ok ? acc1 : -1e30f;
            float mx = fmaxf(l0, l1);
#pragma unroll
            for (int s = 16; s; s >>= 1) mx = fmaxf(mx, __shfl_xor_sync(FULL, mx, s));
            float e0 = __expf(l0 - mx);
            float e1 = v1ok ? __expf(l1 - mx) : 0.f;
            float sm = e0 + e1;
#pragma unroll
            for (int s = 16; s; s >>= 1) sm += __shfl_xor_sync(FULL, sm, s);
            const float inv = 1.f / sm;
            float p0 = e0 * inv;
            float p1 = e1 * inv;   // invalid lanes: exactly 0 (never wins vs >0)
            for (int t = 0; t < 10; t++) {
                unsigned u0 = __float_as_uint(p0);
                unsigned u1 = __float_as_uint(p1);
                unsigned mb = u0 > u1 ? u0 : u1;
                unsigned best = __reduce_max_sync(FULL, mb);
                unsigned m0 = __ballot_sync(FULL, u0 == best);
                unsigned m1 = __ballot_sync(FULL, u1 == best);
                int widx = m0 ? (__ffs(m0) - 1) : (__ffs(m1) - 1 + 32);
                if (lane == 0)
                    s_tk[r * 10 + t] =
                        make_float2(__uint_as_float(best), __int_as_float(widx));
                if (widx == lane)            p0 = 0.f;
                else if (widx == lane + 32)  p1 = 0.f;
            }
        }
    }
    __syncthreads();

    // ---- stage xr into s_hr (plain [62][64]); zero tail (rows 62/63) ----
    {
        const float4* gxr = (const float4*)(P2 + base);
        float4* dst = (float4*)s_hr;
        for (int i = tid; i < 992; i += 256) dst[i] = gxr[i];
        if (tid < 48)
            dst[992 + tid] = make_float4(0.f, 0.f, 0.f, 0.f);
    }
    __syncthreads();

    // ---- Layer 1: h = relu(agg(xr) + rel_b1 + xroot), write paired s_h ----
    {
        const float bi = relb1[col];
        const float* gxo = P3 + base;
        if (tid < 64) {  // zero pad rows 62/63
            s_h[HIDX(62, tid)] = 0.f;
            s_h[HIDX(63, tid)] = 0.f;
        }
#pragma unroll
        for (int t = 0; t < 16; t++) {
            const int r = rg + 4 * t;
            if (r < 62) {
                float acc = bi + gxo[r * 64 + col];
                const float2* tk = s_tk + r * 10;
#pragma unroll
                for (int u = 0; u < 10; u++) {
                    float2 e = tk[u];
                    acc = fmaf(e.x, s_hr[__float_as_int(e.y) * 64 + col], acc);
                }
                s_h[HIDX(r, col)] = fmaxf(acc, 0.f);
            }
        }
    }
    __syncthreads();

    // ---- Layers 2..7: GEMM (h@Wrel -> s_hr, h@Wroot -> regs) + sparse agg ----
    const int pb = rg * 8 * 128;   // paired base: rows (rg+8s, rg+8s+4)
    for (int L = 0; L < 6; L++) {
        // dup weight base, ulonglong2 units: (Lm*32 + kk)*64 + col
        const ulonglong2* WDr =
            (const ulonglong2*)g_Wdup + ((size_t)(L * 2 + 0) * 32) * 64 + col;
        const ulonglong2* WDo =
            (const ulonglong2*)g_Wdup + ((size_t)(L * 2 + 1) * 32) * 64 + col;

        ull aR[8], aO[8];
#pragma unroll
        for (int s = 0; s < 8; s++) { aR[s] = 0ull; aO[s] = 0ull; }

        ulonglong2 wrn = WDr[0];
        ulonglong2 won = WDo[0];
#pragma unroll 2
        for (int kk = 0; kk < 32; kk++) {
            const ulonglong2 wr = wrn, wo = won;
            const int kn = (kk < 31) ? (kk + 1) : 31;   // last: harmless reload
            wrn = WDr[kn * 64];
            won = WDo[kn * 64];
            const float* hp = s_h + pb + kk * 4;
#pragma unroll
            for (int s = 0; s < 8; s++) {
                ulonglong2 hA = *(const ulonglong2*)(hp + s * 128);  // broadcast
                aR[s] = f2(hA.x, wr.x, aR[s]);
                aR[s] = f2(hA.y, wr.y, aR[s]);
                aO[s] = f2(hA.x, wo.x, aO[s]);
                aO[s] = f2(hA.y, wo.y, aO[s]);
            }
        }

        // hr -> smem plain layout
#pragma unroll
        for (int s = 0; s < 8; s++) {
            float2 v = upk(aR[s]);
            const int r0 = rg + 8 * s;
            s_hr[r0 * 64 + col]       = v.x;
            s_hr[(r0 + 4) * 64 + col] = v.y;
        }
        __syncthreads();

        // sparse aggregation + bias + root + relu (+ residual / final output)
        const float brel = brel_mid[L * 64 + col];
        const bool last = (L == 5);
#pragma unroll
        for (int s = 0; s < 8; s++) {
            float2 hro = upk(aO[s]);
            const int r0 = rg + 8 * s;      // always < 62
            const int r1 = r0 + 4;
            {
                float acc = brel + hro.x;
                const float2* tk = s_tk + r0 * 10;
#pragma unroll
                for (int u = 0; u < 10; u++) {
                    float2 e = tk[u];
                    acc = fmaf(e.x, s_hr[__float_as_int(e.y) * 64 + col], acc);
                }
                float v = fmaxf(acc, 0.f);
                const int ha = pb + s * 128 + col * 2;
                if (last) out[base + r0 * 64 + col] = v * P0[base + r0 * 64 + col];
                else      s_h[ha] = s_h[ha] + v;
            }
            if (r1 < 62) {
                float acc = brel + hro.y;
                const float2* tk = s_tk + r1 * 10;
#pragma unroll
                for (int u = 0; u < 10; u++) {
                    float2 e = tk[u];
                    acc = fmaf(e.x, s_hr[__float_as_int(e.y) * 64 + col], acc);
                }
                float v = fmaxf(acc, 0.f);
                const int ha = pb + s * 128 + col * 2 + 1;
                if (last) out[base + r1 * 64 + col] = v * P0[base + r1 * 64 + col];
                else      s_h[ha] = s_h[ha] + v;
            }
        }
        __syncthreads();
    }
}

// ============================================================================
// launch
// ============================================================================
extern "C" void kernel_launch(void* const* d_in, const int* in_sizes, int n_in,
                              void* d_out, int out_size) {
    const float* x        = (const float*)d_in[0];
    const float* gate_w   = (const float*)d_in[1];
    const float* gate_b   = (const float*)d_in[2];
    const float* bnlin_w  = (const float*)d_in[3];
    const float* bnlin_b  = (const float*)d_in[4];
    const float* rel_w1   = (const float*)d_in[5];
    const float* rel_b1   = (const float*)d_in[6];
    const float* root_w1  = (const float*)d_in[7];
    const float* rel_w_m  = (const float*)d_in[8];
    const float* rel_b_m  = (const float*)d_in[9];
    const float* root_w_m = (const float*)d_in[10];
    float* out = (float*)d_out;

    prep_kernel<<<192, 256>>>(rel_w_m, root_w_m);
    proj_kernel<<<dim3(4, 1984), 256>>>(x, gate_w, bnlin_w, rel_w1, root_w1,
                                        gate_b, bnlin_b);
    graph_kernel<<<4096, 256>>>(rel_b_m, rel_b1, out);
}

// round 11
// speedup vs baseline: 1.8244x; 1.0117x over previous
#include <cuda_runtime.h>
#include <math.h>

// ============================================================================
// ResidualGraph: B=4096, C=62, F_IN=256, OUT=BN=64, topK=10
//
// kernel 0 (prep): duplicate mid weights into (w,w) u64 pairs.
// kernel 1 (proj): 4x GEMM [253952,256]@[256,64], BK=32 (16 barriers/CTA).
// kernel 2 (graph): per-batch CTA; ring-buffered h loads in the layer GEMM,
//                   split accumulator chains in softmax + sparse agg.
// ============================================================================

#define PSZ_ ((size_t)253952 * 64)     // elems per projection matrix

// scratch: [m][row][64], m in {mask, xa, xr, xroot}
__device__ float g_P[4 * 253952 * 64];

typedef unsigned long long ull;

// duplicated mid weights: ull index = ((Lm*32 + kk)*64 + col)*2 + (k&1)
__device__ __align__(16) ull g_Wdup[12 * 32 * 64 * 2];

// ---------------- f32x2 packed-FMA helpers (Blackwell FFMA2) ----------------
__device__ __forceinline__ ull pk(float x, float y) {
    ull r;
    asm("mov.b64 %0, {%1, %2};" : "=l"(r)
        : "r"(__float_as_uint(x)), "r"(__float_as_uint(y)));
    return r;
}
__device__ __forceinline__ float2 upk(ull p) {
    unsigned lo, hi;
    asm("mov.b64 {%0, %1}, %2;" : "=r"(lo), "=r"(hi) : "l"(p));
    return make_float2(__uint_as_float(lo), __uint_as_float(hi));
}
__device__ __forceinline__ ull f2(ull a, ull b, ull c) {
    ull d;
    asm("fma.rn.f32x2 %0, %1, %2, %3;" : "=l"(d) : "l"(a), "l"(b), "l"(c));
    return d;
}

// ============================================================================
// Kernel 0: weight duplication. 49152 elements (exactly 192*256 threads).
// ============================================================================
__global__ void prep_kernel(const float* __restrict__ wrel_mid,
                            const float* __restrict__ wroot_mid)
{
    const int i = blockIdx.x * 256 + threadIdx.x;
    const int Lm  = i >> 12;
    const int rem = i & 4095;
    const int k   = rem >> 6;
    const int col = rem & 63;
    const int L   = Lm >> 1;
    const float w = (Lm & 1) ? wroot_mid[L * 4096 + k * 64 + col]
                             : wrel_mid [L * 4096 + k * 64 + col];
    g_Wdup[(((size_t)Lm * 32 + (k >> 1)) * 64 + col) * 2 + (k & 1)] = pk(w, w);
}

// ============================================================================
// Kernel 1: projections. grid = (4, 1984 tiles of 128 rows), 256 threads.
// BK=32: 8 k-tiles, 2 barriers each = 16 barriers/CTA (was 32).
// Lane owns rows 4l..4l+3 x warp's 8-col block (B = warp-broadcast LDS).
// ============================================================================
__global__ __launch_bounds__(256, 3) void proj_kernel(
    const float* __restrict__ X,
    const float* __restrict__ Wg, const float* __restrict__ Wb,
    const float* __restrict__ Wr, const float* __restrict__ Wo,
    const float* __restrict__ gb, const float* __restrict__ bb)
{
    __shared__ __align__(16) float As[32 * 132];   // As[k][row], pitch 132
    __shared__ __align__(16) ull   Bs[32 * 64];    // Bs[k][col] duplicated

    const int tid = threadIdx.x;
    const int m   = blockIdx.x;
    const float* W = (m == 0) ? Wg : (m == 1) ? Wb : (m == 2) ? Wr : Wo;

    const int lane = tid & 31, wrp = tid >> 5;
    const size_t rowBase = (size_t)blockIdx.y * 128;

    // staging roles
    const int ar = tid >> 1;            // 0..127 (A row)
    const int ak = (tid & 1) * 16;      // k sub-block 0 / 16
    const int bk = tid >> 3;            // 0..31 (B k-row)
    const int bq = tid & 7;             // col octet
    const float* Ag = X + (rowBase + ar) * 256 + ak;
    const float* Bg = W + bk * 64 + bq * 8;

    ull acc[2][8];
#pragma unroll
    for (int rp = 0; rp < 2; rp++)
#pragma unroll
        for (int c = 0; c < 8; c++) acc[rp][c] = 0ull;

    float4 av0 = *(const float4*)(Ag);
    float4 av1 = *(const float4*)(Ag + 4);
    float4 av2 = *(const float4*)(Ag + 8);
    float4 av3 = *(const float4*)(Ag + 12);
    float4 bv0 = *(const float4*)(Bg);
    float4 bv1 = *(const float4*)(Bg + 4);

    for (int k0 = 0; k0 < 256; k0 += 32) {
        __syncthreads();
        As[(ak + 0)  * 132 + ar] = av0.x;
        As[(ak + 1)  * 132 + ar] = av0.y;
        As[(ak + 2)  * 132 + ar] = av0.z;
        As[(ak + 3)  * 132 + ar] = av0.w;
        As[(ak + 4)  * 132 + ar] = av1.x;
        As[(ak + 5)  * 132 + ar] = av1.y;
        As[(ak + 6)  * 132 + ar] = av1.z;
        As[(ak + 7)  * 132 + ar] = av1.w;
        As[(ak + 8)  * 132 + ar] = av2.x;
        As[(ak + 9)  * 132 + ar] = av2.y;
        As[(ak + 10) * 132 + ar] = av2.z;
        As[(ak + 11) * 132 + ar] = av2.w;
        As[(ak + 12) * 132 + ar] = av3.x;
        As[(ak + 13) * 132 + ar] = av3.y;
        As[(ak + 14) * 132 + ar] = av3.z;
        As[(ak + 15) * 132 + ar] = av3.w;
        {
            ull* bd = Bs + bk * 64 + bq * 8;
            bd[0] = pk(bv0.x, bv0.x);
            bd[1] = pk(bv0.y, bv0.y);
            bd[2] = pk(bv0.z, bv0.z);
            bd[3] = pk(bv0.w, bv0.w);
            bd[4] = pk(bv1.x, bv1.x);
            bd[5] = pk(bv1.y, bv1.y);
            bd[6] = pk(bv1.z, bv1.z);
            bd[7] = pk(bv1.w, bv1.w);
        }
        __syncthreads();
        if (k0 + 32 < 256) {                       // prefetch next tile
            av0 = *(const float4*)(Ag + k0 + 32);
            av1 = *(const float4*)(Ag + k0 + 36);
            av2 = *(const float4*)(Ag + k0 + 40);
            av3 = *(const float4*)(Ag + k0 + 44);
            bv0 = *(const float4*)(Bg + (k0 + 32) * 64);
            bv1 = *(const float4*)(Bg + (k0 + 32) * 64 + 4);
        }
#pragma unroll
        for (int k = 0; k < 32; k++) {
            ulonglong2 a2 = *(const ulonglong2*)(As + k * 132 + lane * 4);
            const ull* bp = Bs + k * 64 + wrp * 8;
            ulonglong2 b01 = *(const ulonglong2*)(bp);
            ulonglong2 b23 = *(const ulonglong2*)(bp + 2);
            ulonglong2 b45 = *(const ulonglong2*)(bp + 4);
            ulonglong2 b67 = *(const ulonglong2*)(bp + 6);
            acc[0][0] = f2(a2.x, b01.x, acc[0][0]);
            acc[0][1] = f2(a2.x, b01.y, acc[0][1]);
            acc[0][2] = f2(a2.x, b23.x, acc[0][2]);
            acc[0][3] = f2(a2.x, b23.y, acc[0][3]);
            acc[0][4] = f2(a2.x, b45.x, acc[0][4]);
            acc[0][5] = f2(a2.x, b45.y, acc[0][5]);
            acc[0][6] = f2(a2.x, b67.x, acc[0][6]);
            acc[0][7] = f2(a2.x, b67.y, acc[0][7]);
            acc[1][0] = f2(a2.y, b01.x, acc[1][0]);
            acc[1][1] = f2(a2.y, b01.y, acc[1][1]);
            acc[1][2] = f2(a2.y, b23.x, acc[1][2]);
            acc[1][3] = f2(a2.y, b23.y, acc[1][3]);
            acc[1][4] = f2(a2.y, b45.x, acc[1][4]);
            acc[1][5] = f2(a2.y, b45.y, acc[1][5]);
            acc[1][6] = f2(a2.y, b67.x, acc[1][6]);
            acc[1][7] = f2(a2.y, b67.y, acc[1][7]);
        }
    }

    float bia[8];
#pragma unroll
    for (int c = 0; c < 8; c++) bia[c] = 0.f;
    if (m == 0) {
        float4 t0 = *(const float4*)(gb + wrp * 8);
        float4 t1 = *(const float4*)(gb + wrp * 8 + 4);
        bia[0] = t0.x; bia[1] = t0.y; bia[2] = t0.z; bia[3] = t0.w;
        bia[4] = t1.x; bia[5] = t1.y; bia[6] = t1.z; bia[7] = t1.w;
    } else if (m == 1) {
        float4 t0 = *(const float4*)(bb + wrp * 8);
        float4 t1 = *(const float4*)(bb + wrp * 8 + 4);
        bia[0] = t0.x; bia[1] = t0.y; bia[2] = t0.z; bia[3] = t0.w;
        bia[4] = t1.x; bia[5] = t1.y; bia[6] = t1.z; bia[7] = t1.w;
    }

    float* Pm = g_P + (size_t)m * PSZ_ + rowBase * 64;
#pragma unroll
    for (int rp = 0; rp < 2; rp++) {
        float2 c0 = upk(acc[rp][0]), c1 = upk(acc[rp][1]);
        float2 c2 = upk(acc[rp][2]), c3 = upk(acc[rp][3]);
        float2 c4 = upk(acc[rp][4]), c5 = upk(acc[rp][5]);
        float2 c6 = upk(acc[rp][6]), c7 = upk(acc[rp][7]);
#pragma unroll
        for (int j = 0; j < 2; j++) {
            const int row = lane * 4 + rp * 2 + j;
            float4 lo, hi;
            lo.x = j ? c0.y : c0.x;  lo.y = j ? c1.y : c1.x;
            lo.z = j ? c2.y : c2.x;  lo.w = j ? c3.y : c3.x;
            hi.x = j ? c4.y : c4.x;  hi.y = j ? c5.y : c5.x;
            hi.z = j ? c6.y : c6.x;  hi.w = j ? c7.y : c7.x;
            if (m < 2) {
                lo.x = tanhf(lo.x + bia[0]); lo.y = tanhf(lo.y + bia[1]);
                lo.z = tanhf(lo.z + bia[2]); lo.w = tanhf(lo.w + bia[3]);
                hi.x = tanhf(hi.x + bia[4]); hi.y = tanhf(hi.y + bia[5]);
                hi.z = tanhf(hi.z + bia[6]); hi.w = tanhf(hi.w + bia[7]);
            }
            float* dst = Pm + (size_t)row * 64 + wrp * 8;
            *(float4*)(dst)     = lo;
            *(float4*)(dst + 4) = hi;
        }
    }
}

// ============================================================================
// Kernel 2: per-batch graph phase. grid = 4096 CTAs x 256 threads.
// Paired h layout: H(r,c) = ((r&3)*8 + (r>>3))*128 + c*2 + ((r>>2)&1)
// ============================================================================
#define HIDX(r, c) ((((r) & 3) * 8 + ((r) >> 3)) * 128 + (c) * 2 + (((r) >> 2) & 1))

// one dual-FMA group for pair s
#define GEMM_STEP(s, hv)                                   \
    aR[s] = f2((hv).x, wr.x, aR[s]);                       \
    aR[s] = f2((hv).y, wr.y, aR[s]);                       \
    aO[s] = f2((hv).x, wo.x, aO[s]);                       \
    aO[s] = f2((hv).y, wo.y, aO[s]);

__global__ __launch_bounds__(256, 3) void graph_kernel(
    const float* __restrict__ brel_mid,
    const float* __restrict__ relb1,
    float* __restrict__ out)
{
    __shared__ __align__(16) float  s_h[4096];
    __shared__ __align__(16) float  s_hr[4160];
    __shared__ __align__(16) float2 s_tk[620];

    const int tid = threadIdx.x;
    const int rg  = tid >> 6;
    const int col = tid & 63;
    const size_t base = (size_t)blockIdx.x * 3968;

    const float* P0 = g_P;                 // x_mask
    const float* P1 = g_P + PSZ_;          // xa
    const float* P2 = g_P + 2 * PSZ_;      // xr
    const float* P3 = g_P + 3 * PSZ_;      // xroot

    // ---- Phase A1: load xa plain (s_h) + transposed pitch-65 (s_hr) ----
    {
        const float* gxa = P1 + base;
        for (int i = tid; i < 3968; i += 256) {
            float v = gxa[i];
            s_h[i] = v;
            s_hr[(i & 63) * 65 + (i >> 6)] = v;
        }
    }
    __syncthreads();

    // ---- Phase A2: logits + softmax + top-10 (warp per row) ----
    {
        const int warp = tid >> 5, lane = tid & 31;
        const unsigned FULL = 0xFFFFFFFFu;
        for (int r = warp; r < 62; r += 8) {
            const float* xaR = s_h + r * 64;
            float a00 = 0.f, a01 = 0.f, a10 = 0.f, a11 = 0.f;
#pragma unroll
            for (int k = 0; k < 64; k += 2) {
                float x0 = xaR[k], x1 = xaR[k + 1];
                a00 = fmaf(x0, s_hr[k * 65 + lane], a00);
                a10 = fmaf(x0, s_hr[k * 65 + lane + 32], a10);
                a01 = fmaf(x1, s_hr[(k + 1) * 65 + lane], a01);
                a11 = fmaf(x1, s_hr[(k + 1) * 65 + lane + 32], a11);
            }
            const bool v1ok = (lane + 32) < 62;
            float l0 = a00 + a01;
            float l1 = v1ok ? (a10 + a11) : -1e30f;
            float mx = fmaxf(l0, l1);
#pragma unroll
            for (int s = 16; s; s >>= 1) mx = fmaxf(mx, __shfl_xor_sync(FULL, mx, s));
            float e0 = __expf(l0 - mx);
            float e1 = v1ok ? __expf(l1 - mx) : 0.f;
            float sm = e0 + e1;
#pragma unroll
            for (int s = 16; s; s >>= 1) sm += __shfl_xor_sync(FULL, sm, s);
            const float inv = 1.f / sm;
            float p0 = e0 * inv;
            float p1 = e1 * inv;   // invalid lanes: exactly 0 (never wins vs >0)
            for (int t = 0; t < 10; t++) {
                unsigned u0 = __float_as_uint(p0);
                unsigned u1 = __float_as_uint(p1);
                unsigned mb = u0 > u1 ? u0 : u1;
                unsigned best = __reduce_max_sync(FULL, mb);
                unsigned m0 = __ballot_sync(FULL, u0 == best);
                unsigned m1 = __ballot_sync(FULL, u1 == best);
                int widx = m0 ? (__ffs(m0) - 1) : (__ffs(m1) - 1 + 32);
                if (lane == 0)
                    s_tk[r * 10 + t] =
                        make_float2(__uint_as_float(best), __int_as_float(widx));
                if (widx == lane)            p0 = 0.f;
                else if (widx == lane + 32)  p1 = 0.f;
            }
        }
    }
    __syncthreads();

    // ---- stage xr into s_hr (plain [62][64]); zero tail (rows 62/63) ----
    {
        const float4* gxr = (const float4*)(P2 + base);
        float4* dst = (float4*)s_hr;
        for (int i = tid; i < 992; i += 256) dst[i] = gxr[i];
        if (tid < 48)
            dst[992 + tid] = make_float4(0.f, 0.f, 0.f, 0.f);
    }
    __syncthreads();

    // ---- Layer 1: h = relu(agg(xr) + rel_b1 + xroot), write paired s_h ----
    {
        const float bi = relb1[col];
        const float* gxo = P3 + base;
        if (tid < 64) {  // zero pad rows 62/63
            s_h[HIDX(62, tid)] = 0.f;
            s_h[HIDX(63, tid)] = 0.f;
        }
#pragma unroll
        for (int t = 0; t < 16; t++) {
            const int r = rg + 4 * t;
            if (r < 62) {
                float aa = bi + gxo[r * 64 + col];
                float ab = 0.f;
                const float2* tk = s_tk + r * 10;
#pragma unroll
                for (int u = 0; u < 10; u += 2) {
                    float2 e0 = tk[u], e1 = tk[u + 1];
                    aa = fmaf(e0.x, s_hr[__float_as_int(e0.y) * 64 + col], aa);
                    ab = fmaf(e1.x, s_hr[__float_as_int(e1.y) * 64 + col], ab);
                }
                s_h[HIDX(r, col)] = fmaxf(aa + ab, 0.f);
            }
        }
    }
    __syncthreads();

    // ---- Layers 2..7: GEMM (h@Wrel -> s_hr, h@Wroot -> regs) + sparse agg ----
    const int pb = rg * 8 * 128;   // paired base: rows (rg+8s, rg+8s+4)
    for (int L = 0; L < 6; L++) {
        const ulonglong2* WDr =
            (const ulonglong2*)g_Wdup + ((size_t)(L * 2 + 0) * 32) * 64 + col;
        const ulonglong2* WDo =
            (const ulonglong2*)g_Wdup + ((size_t)(L * 2 + 1) * 32) * 64 + col;

        ull aR[8], aO[8];
#pragma unroll
        for (int s = 0; s < 8; s++) { aR[s] = 0ull; aO[s] = 0ull; }

        ulonglong2 wrn = WDr[0];
        ulonglong2 won = WDo[0];
#pragma unroll 2
        for (int kk = 0; kk < 32; kk++) {
            const ulonglong2 wr = wrn, wo = won;
            const int kn = (kk < 31) ? (kk + 1) : 31;   // last: harmless reload
            wrn = WDr[kn * 64];
            won = WDo[kn * 64];
            const float* hp = s_h + pb + kk * 4;
            // ring-buffered loads: 5 up-front, remaining 3 interleaved, so
            // the first consumer is >=5 LDS behind its producer and 4-8
            // loads are always in flight.
            ulonglong2 h0 = *(const ulonglong2*)(hp);
            ulonglong2 h1 = *(const ulonglong2*)(hp + 128);
            ulonglong2 h2 = *(const ulonglong2*)(hp + 256);
            ulonglong2 h3 = *(const ulonglong2*)(hp + 384);
            ulonglong2 h4 = *(const ulonglong2*)(hp + 512);
            GEMM_STEP(0, h0)
            ulonglong2 h5 = *(const ulonglong2*)(hp + 640);
            GEMM_STEP(1, h1)
            ulonglong2 h6 = *(const ulonglong2*)(hp + 768);
            GEMM_STEP(2, h2)
            ulonglong2 h7 = *(const ulonglong2*)(hp + 896);
            GEMM_STEP(3, h3)
            GEMM_STEP(4, h4)
            GEMM_STEP(5, h5)
            GEMM_STEP(6, h6)
            GEMM_STEP(7, h7)
        }

        // hr -> smem plain layout
#pragma unroll
        for (int s = 0; s < 8; s++) {
            float2 v = upk(aR[s]);
            const int r0 = rg + 8 * s;
            s_hr[r0 * 64 + col]       = v.x;
            s_hr[(r0 + 4) * 64 + col] = v.y;
        }
        __syncthreads();

        // sparse aggregation + bias + root + relu (+ residual / final output)
        const float brel = brel_mid[L * 64 + col];
        const bool last = (L == 5);
#pragma unroll
        for (int s = 0; s < 8; s++) {
            float2 hro = upk(aO[s]);
            const int r0 = rg + 8 * s;      // always < 62
            const int r1 = r0 + 4;
            {
                float aa = brel + hro.x;
                float ab = 0.f;
                const float2* tk = s_tk + r0 * 10;
#pragma unroll
                for (int u = 0; u < 10; u += 2) {
                    float2 e0 = tk[u], e1 = tk[u + 1];
                    aa = fmaf(e0.x, s_hr[__float_as_int(e0.y) * 64 + col], aa);
                    ab = fmaf(e1.x, s_hr[__float_as_int(e1.y) * 64 + col], ab);
                }
                float v = fmaxf(aa + ab, 0.f);
                const int ha = pb + s * 128 + col * 2;
                if (last) out[base + r0 * 64 + col] = v * P0[base + r0 * 64 + col];
                else      s_h[ha] = s_h[ha] + v;
            }
            if (r1 < 62) {
                float aa = brel + hro.y;
                float ab = 0.f;
                const float2* tk = s_tk + r1 * 10;
#pragma unroll
                for (int u = 0; u < 10; u += 2) {
                    float2 e0 = tk[u], e1 = tk[u + 1];
                    aa = fmaf(e0.x, s_hr[__float_as_int(e0.y) * 64 + col], aa);
                    ab = fmaf(e1.x, s_hr[__float_as_int(e1.y) * 64 + col], ab);
                }
                float v = fmaxf(aa + ab, 0.f);
                const int ha = pb + s * 128 + col * 2 + 1;
                if (last) out[base + r1 * 64 + col] = v * P0[base + r1 * 64 + col];
                else      s_h[ha] = s_h[ha] + v;
            }
        }
        __syncthreads();
    }
}

// ============================================================================
// launch
// ============================================================================
extern "C" void kernel_launch(void* const* d_in, const int* in_sizes, int n_in,
                              void* d_out, int out_size) {
    const float* x        = (const float*)d_in[0];
    const float* gate_w   = (const float*)d_in[1];
    const float* gate_b   = (const float*)d_in[2];
    const float* bnlin_w  = (const float*)d_in[3];
    const float* bnlin_b  = (const float*)d_in[4];
    const float* rel_w1   = (const float*)d_in[5];
    const float* rel_b1   = (const float*)d_in[6];
    const float* root_w1  = (const float*)d_in[7];
    const float* rel_w_m  = (const float*)d_in[8];
    const float* rel_b_m  = (const float*)d_in[9];
    const float* root_w_m = (const float*)d_in[10];
    float* out = (float*)d_out;

    prep_kernel<<<192, 256>>>(rel_w_m, root_w_m);
    proj_kernel<<<dim3(4, 1984), 256>>>(x, gate_w, bnlin_w, rel_w1, root_w1,
                                        gate_b, bnlin_b);
    graph_kernel<<<4096, 256>>>(rel_b_m, rel_b1, out);
}

// round 15
// speedup vs baseline: 1.8584x; 1.0187x over previous
#include <cuda_runtime.h>
#include <math.h>

// ============================================================================
// ResidualGraph: B=4096, C=62, F_IN=256, OUT=BN=64, topK=10
//
// kernel 1 (proj): 4x GEMM [253952,256]@[256,64], BK=32; blockIdx.y==1984
//                  rows do the weight-duplication prep (merged -> 2-kernel
//                  launch pattern so ncu -s5-c1 lands on graph_kernel).
// kernel 2 (graph): per-batch CTA; Phase A2 now 4-row register-tiled
//                  (halves A2 smem wavefronts: 6 LDS per k per 4 rows).
// ============================================================================

#define PSZ_ ((size_t)253952 * 64)     // elems per projection matrix

// scratch: [m][row][64], m in {mask, xa, xr, xroot}
__device__ float g_P[4 * 253952 * 64];

typedef unsigned long long ull;

// duplicated mid weights: ull index = ((Lm*32 + kk)*64 + col)*2 + (k&1)
__device__ __align__(16) ull g_Wdup[12 * 32 * 64 * 2];

// ---------------- f32x2 packed-FMA helpers (Blackwell FFMA2) ----------------
__device__ __forceinline__ ull pk(float x, float y) {
    ull r;
    asm("mov.b64 %0, {%1, %2};" : "=l"(r)
        : "r"(__float_as_uint(x)), "r"(__float_as_uint(y)));
    return r;
}
__device__ __forceinline__ float2 upk(ull p) {
    unsigned lo, hi;
    asm("mov.b64 {%0, %1}, %2;" : "=r"(lo), "=r"(hi) : "l"(p));
    return make_float2(__uint_as_float(lo), __uint_as_float(hi));
}
__device__ __forceinline__ ull f2(ull a, ull b, ull c) {
    ull d;
    asm("fma.rn.f32x2 %0, %1, %2, %3;" : "=l"(d) : "l"(a), "l"(b), "l"(c));
    return d;
}

// ============================================================================
// Kernel 1: projections + merged prep. grid = (4, 1985), 256 threads.
// ============================================================================
__global__ __launch_bounds__(256, 3) void proj_kernel(
    const float* __restrict__ X,
    const float* __restrict__ Wg, const float* __restrict__ Wb,
    const float* __restrict__ Wr, const float* __restrict__ Wo,
    const float* __restrict__ gb, const float* __restrict__ bb,
    const float* __restrict__ wrel_mid, const float* __restrict__ wroot_mid)
{
    __shared__ __align__(16) float As[32 * 132];   // As[k][row], pitch 132
    __shared__ __align__(16) ull   Bs[32 * 64];    // Bs[k][col] duplicated

    const int tid = threadIdx.x;
    const int m   = blockIdx.x;

    if (blockIdx.y == 1984) {
        // ---- merged prep: duplicate mid weights into (w,w) u64 pairs ----
        int i = (m * 256 + tid) * 48;
        for (int e = 0; e < 48; e++, i++) {
            const int Lm  = i >> 12;
            const int rem = i & 4095;
            const int k   = rem >> 6;
            const int col = rem & 63;
            const int L   = Lm >> 1;
            const float w = (Lm & 1) ? wroot_mid[L * 4096 + k * 64 + col]
                                     : wrel_mid [L * 4096 + k * 64 + col];
            g_Wdup[(((size_t)Lm * 32 + (k >> 1)) * 64 + col) * 2 + (k & 1)] =
                pk(w, w);
        }
        return;
    }

    const float* W = (m == 0) ? Wg : (m == 1) ? Wb : (m == 2) ? Wr : Wo;

    const int lane = tid & 31, wrp = tid >> 5;
    const size_t rowBase = (size_t)blockIdx.y * 128;

    const int ar = tid >> 1;            // 0..127 (A row)
    const int ak = (tid & 1) * 16;      // k sub-block 0 / 16
    const int bk = tid >> 3;            // 0..31 (B k-row)
    const int bq = tid & 7;             // col octet
    const float* Ag = X + (rowBase + ar) * 256 + ak;
    const float* Bg = W + bk * 64 + bq * 8;

    ull acc[2][8];
#pragma unroll
    for (int rp = 0; rp < 2; rp++)
#pragma unroll
        for (int c = 0; c < 8; c++) acc[rp][c] = 0ull;

    float4 av0 = *(const float4*)(Ag);
    float4 av1 = *(const float4*)(Ag + 4);
    float4 av2 = *(const float4*)(Ag + 8);
    float4 av3 = *(const float4*)(Ag + 12);
    float4 bv0 = *(const float4*)(Bg);
    float4 bv1 = *(const float4*)(Bg + 4);

    for (int k0 = 0; k0 < 256; k0 += 32) {
        __syncthreads();
        As[(ak + 0)  * 132 + ar] = av0.x;
        As[(ak + 1)  * 132 + ar] = av0.y;
        As[(ak + 2)  * 132 + ar] = av0.z;
        As[(ak + 3)  * 132 + ar] = av0.w;
        As[(ak + 4)  * 132 + ar] = av1.x;
        As[(ak + 5)  * 132 + ar] = av1.y;
        As[(ak + 6)  * 132 + ar] = av1.z;
        As[(ak + 7)  * 132 + ar] = av1.w;
        As[(ak + 8)  * 132 + ar] = av2.x;
        As[(ak + 9)  * 132 + ar] = av2.y;
        As[(ak + 10) * 132 + ar] = av2.z;
        As[(ak + 11) * 132 + ar] = av2.w;
        As[(ak + 12) * 132 + ar] = av3.x;
        As[(ak + 13) * 132 + ar] = av3.y;
        As[(ak + 14) * 132 + ar] = av3.z;
        As[(ak + 15) * 132 + ar] = av3.w;
        {
            ull* bd = Bs + bk * 64 + bq * 8;
            bd[0] = pk(bv0.x, bv0.x);
            bd[1] = pk(bv0.y, bv0.y);
            bd[2] = pk(bv0.z, bv0.z);
            bd[3] = pk(bv0.w, bv0.w);
            bd[4] = pk(bv1.x, bv1.x);
            bd[5] = pk(bv1.y, bv1.y);
            bd[6] = pk(bv1.z, bv1.z);
            bd[7] = pk(bv1.w, bv1.w);
        }
        __syncthreads();
        if (k0 + 32 < 256) {                       // prefetch next tile
            av0 = *(const float4*)(Ag + k0 + 32);
            av1 = *(const float4*)(Ag + k0 + 36);
            av2 = *(const float4*)(Ag + k0 + 40);
            av3 = *(const float4*)(Ag + k0 + 44);
            bv0 = *(const float4*)(Bg + (k0 + 32) * 64);
            bv1 = *(const float4*)(Bg + (k0 + 32) * 64 + 4);
        }
#pragma unroll
        for (int k = 0; k < 32; k++) {
            ulonglong2 a2 = *(const ulonglong2*)(As + k * 132 + lane * 4);
            const ull* bp = Bs + k * 64 + wrp * 8;
            ulonglong2 b01 = *(const ulonglong2*)(bp);
            ulonglong2 b23 = *(const ulonglong2*)(bp + 2);
            ulonglong2 b45 = *(const ulonglong2*)(bp + 4);
            ulonglong2 b67 = *(const ulonglong2*)(bp + 6);
            acc[0][0] = f2(a2.x, b01.x, acc[0][0]);
            acc[0][1] = f2(a2.x, b01.y, acc[0][1]);
            acc[0][2] = f2(a2.x, b23.x, acc[0][2]);
            acc[0][3] = f2(a2.x, b23.y, acc[0][3]);
            acc[0][4] = f2(a2.x, b45.x, acc[0][4]);
            acc[0][5] = f2(a2.x, b45.y, acc[0][5]);
            acc[0][6] = f2(a2.x, b67.x, acc[0][6]);
            acc[0][7] = f2(a2.x, b67.y, acc[0][7]);
            acc[1][0] = f2(a2.y, b01.x, acc[1][0]);
            acc[1][1] = f2(a2.y, b01.y, acc[1][1]);
            acc[1][2] = f2(a2.y, b23.x, acc[1][2]);
            acc[1][3] = f2(a2.y, b23.y, acc[1][3]);
            acc[1][4] = f2(a2.y, b45.x, acc[1][4]);
            acc[1][5] = f2(a2.y, b45.y, acc[1][5]);
            acc[1][6] = f2(a2.y, b67.x, acc[1][6]);
            acc[1][7] = f2(a2.y, b67.y, acc[1][7]);
        }
    }

    float bia[8];
#pragma unroll
    for (int c = 0; c < 8; c++) bia[c] = 0.f;
    if (m == 0) {
        float4 t0 = *(const float4*)(gb + wrp * 8);
        float4 t1 = *(const float4*)(gb + wrp * 8 + 4);
        bia[0] = t0.x; bia[1] = t0.y; bia[2] = t0.z; bia[3] = t0.w;
        bia[4] = t1.x; bia[5] = t1.y; bia[6] = t1.z; bia[7] = t1.w;
    } else if (m == 1) {
        float4 t0 = *(const float4*)(bb + wrp * 8);
        float4 t1 = *(const float4*)(bb + wrp * 8 + 4);
        bia[0] = t0.x; bia[1] = t0.y; bia[2] = t0.z; bia[3] = t0.w;
        bia[4] = t1.x; bia[5] = t1.y; bia[6] = t1.z; bia[7] = t1.w;
    }

    float* Pm = g_P + (size_t)m * PSZ_ + rowBase * 64;
#pragma unroll
    for (int rp = 0; rp < 2; rp++) {
        float2 c0 = upk(acc[rp][0]), c1 = upk(acc[rp][1]);
        float2 c2 = upk(acc[rp][2]), c3 = upk(acc[rp][3]);
        float2 c4 = upk(acc[rp][4]), c5 = upk(acc[rp][5]);
        float2 c6 = upk(acc[rp][6]), c7 = upk(acc[rp][7]);
#pragma unroll
        for (int j = 0; j < 2; j++) {
            const int row = lane * 4 + rp * 2 + j;
            float4 lo, hi;
            lo.x = j ? c0.y : c0.x;  lo.y = j ? c1.y : c1.x;
            lo.z = j ? c2.y : c2.x;  lo.w = j ? c3.y : c3.x;
            hi.x = j ? c4.y : c4.x;  hi.y = j ? c5.y : c5.x;
            hi.z = j ? c6.y : c6.x;  hi.w = j ? c7.y : c7.x;
            if (m < 2) {
                lo.x = tanhf(lo.x + bia[0]); lo.y = tanhf(lo.y + bia[1]);
                lo.z = tanhf(lo.z + bia[2]); lo.w = tanhf(lo.w + bia[3]);
                hi.x = tanhf(hi.x + bia[4]); hi.y = tanhf(hi.y + bia[5]);
                hi.z = tanhf(hi.z + bia[6]); hi.w = tanhf(hi.w + bia[7]);
            }
            float* dst = Pm + (size_t)row * 64 + wrp * 8;
            *(float4*)(dst)     = lo;
            *(float4*)(dst + 4) = hi;
        }
    }
}

// ============================================================================
// Kernel 2: per-batch graph phase. grid = 4096 CTAs x 256 threads.
// Paired h layout: H(r,c) = ((r&3)*8 + (r>>3))*128 + c*2 + ((r>>2)&1)
// Phase A2 v2: warp computes 4 rows at once -> 6 LDS per k per 4 rows
// (2 column loads shared + 4 row broadcasts), half the previous traffic.
// ============================================================================
#define HIDX(r, c) ((((r) & 3) * 8 + ((r) >> 3)) * 128 + (c) * 2 + (((r) >> 2) & 1))

// one dual-FMA group for pair s
#define GEMM_STEP(s, hv)                                   \
    aR[s] = f2((hv).x, wr.x, aR[s]);                       \
    aR[s] = f2((hv).y, wr.y, aR[s]);                       \
    aO[s] = f2((hv).x, wo.x, aO[s]);                       \
    aO[s] = f2((hv).y, wo.y, aO[s]);

__global__ __launch_bounds__(256, 3) void graph_kernel(
    const float* __restrict__ brel_mid,
    const float* __restrict__ relb1,
    float* __restrict__ out)
{
    __shared__ __align__(16) float  s_h[4096];
    __shared__ __align__(16) float  s_hr[4160];
    __shared__ __align__(16) float2 s_tk[620];

    const int tid = threadIdx.x;
    const int rg  = tid >> 6;
    const int col = tid & 63;
    const size_t base = (size_t)blockIdx.x * 3968;

    const float* P0 = g_P;                 // x_mask
    const float* P1 = g_P + PSZ_;          // xa
    const float* P2 = g_P + 2 * PSZ_;      // xr
    const float* P3 = g_P + 3 * PSZ_;      // xroot

    // ---- Phase A1: load xa plain (s_h) + transposed pitch-65 (s_hr) ----
    {
        const float* gxa = P1 + base;
        for (int i = tid; i < 3968; i += 256) {
            float v = gxa[i];
            s_h[i] = v;
            s_hr[(i & 63) * 65 + (i >> 6)] = v;
        }
        // zero rows 62/63 of the plain copy: phase A2 group 15 reads them
        // as row operands (results discarded, but keep the reads defined)
        if (tid < 128) s_h[3968 + tid] = 0.f;
    }
    __syncthreads();

    // ---- Phase A2: logits + softmax + top-10 (warp per 4 rows) ----
    {
        const int warp = tid >> 5, lane = tid & 31;
        const unsigned FULL = 0xFFFFFFFFu;
        for (int it = 0; it < 2; it++) {
            const int g  = warp + 8 * it;      // group 0..15
            const int rb = g * 4;              // first row of group
            float ac[4][2];
#pragma unroll
            for (int j = 0; j < 4; j++) { ac[j][0] = 0.f; ac[j][1] = 0.f; }
            const float* xa0 = s_h + (rb + 0) * 64;
            const float* xa1 = s_h + (rb + 1) * 64;
            const float* xa2 = s_h + (rb + 2) * 64;
            const float* xa3 = s_h + (rb + 3) * 64;
#pragma unroll 8
            for (int k = 0; k < 64; k++) {
                const float c0 = s_hr[k * 65 + lane];
                const float c1 = s_hr[k * 65 + lane + 32];
                const float x0 = xa0[k], x1 = xa1[k];
                const float x2 = xa2[k], x3 = xa3[k];
                ac[0][0] = fmaf(x0, c0, ac[0][0]);
                ac[0][1] = fmaf(x0, c1, ac[0][1]);
                ac[1][0] = fmaf(x1, c0, ac[1][0]);
                ac[1][1] = fmaf(x1, c1, ac[1][1]);
                ac[2][0] = fmaf(x2, c0, ac[2][0]);
                ac[2][1] = fmaf(x2, c1, ac[2][1]);
                ac[3][0] = fmaf(x3, c0, ac[3][0]);
                ac[3][1] = fmaf(x3, c1, ac[3][1]);
            }
            const bool v1ok = (lane + 32) < 62;
#pragma unroll
            for (int j = 0; j < 4; j++) {
                const int r = rb + j;
                if (r >= 62) break;
                float l0 = ac[j][0];
                float l1 = v1ok ? ac[j][1] : -1e30f;
                float mx = fmaxf(l0, l1);
#pragma unroll
                for (int s = 16; s; s >>= 1)
                    mx = fmaxf(mx, __shfl_xor_sync(FULL, mx, s));
                float e0 = __expf(l0 - mx);
                float e1 = v1ok ? __expf(l1 - mx) : 0.f;
                float sm = e0 + e1;
#pragma unroll
                for (int s = 16; s; s >>= 1)
                    sm += __shfl_xor_sync(FULL, sm, s);
                const float inv = 1.f / sm;
                float p0 = e0 * inv;
                float p1 = e1 * inv;   // invalid lanes: exactly 0
                for (int t = 0; t < 10; t++) {
                    unsigned u0 = __float_as_uint(p0);
                    unsigned u1 = __float_as_uint(p1);
                    unsigned mb = u0 > u1 ? u0 : u1;
                    unsigned best = __reduce_max_sync(FULL, mb);
                    unsigned m0 = __ballot_sync(FULL, u0 == best);
                    unsigned m1 = __ballot_sync(FULL, u1 == best);
                    int widx = m0 ? (__ffs(m0) - 1) : (__ffs(m1) - 1 + 32);
                    if (lane == 0)
                        s_tk[r * 10 + t] =
                            make_float2(__uint_as_float(best),
                                        __int_as_float(widx));
                    if (widx == lane)            p0 = 0.f;
                    else if (widx == lane + 32)  p1 = 0.f;
                }
            }
        }
    }
    __syncthreads();

    // ---- stage xr into s_hr (plain [62][64]); zero tail (rows 62/63) ----
    {
        const float4* gxr = (const float4*)(P2 + base);
        float4* dst = (float4*)s_hr;
        for (int i = tid; i < 992; i += 256) dst[i] = gxr[i];
        if (tid < 48)
            dst[992 + tid] = make_float4(0.f, 0.f, 0.f, 0.f);
    }
    __syncthreads();

    // ---- Layer 1: h = relu(agg(xr) + rel_b1 + xroot), write paired s_h ----
    {
        const float bi = relb1[col];
        const float* gxo = P3 + base;
        if (tid < 64) {  // zero pad rows 62/63
            s_h[HIDX(62, tid)] = 0.f;
            s_h[HIDX(63, tid)] = 0.f;
        }
#pragma unroll
        for (int t = 0; t < 16; t++) {
            const int r = rg + 4 * t;
            if (r < 62) {
                float aa = bi + gxo[r * 64 + col];
                float ab = 0.f;
                const float2* tk = s_tk + r * 10;
#pragma unroll
                for (int u = 0; u < 10; u += 2) {
                    float2 e0 = tk[u], e1 = tk[u + 1];
                    aa = fmaf(e0.x, s_hr[__float_as_int(e0.y) * 64 + col], aa);
                    ab = fmaf(e1.x, s_hr[__float_as_int(e1.y) * 64 + col], ab);
                }
                s_h[HIDX(r, col)] = fmaxf(aa + ab, 0.f);
            }
        }
    }
    __syncthreads();

    // ---- Layers 2..7: GEMM (h@Wrel -> s_hr, h@Wroot -> regs) + sparse agg ----
    const int pb = rg * 8 * 128;   // paired base: rows (rg+8s, rg+8s+4)
    for (int L = 0; L < 6; L++) {
        const ulonglong2* WDr =
            (const ulonglong2*)g_Wdup + ((size_t)(L * 2 + 0) * 32) * 64 + col;
        const ulonglong2* WDo =
            (const ulonglong2*)g_Wdup + ((size_t)(L * 2 + 1) * 32) * 64 + col;

        ull aR[8], aO[8];
#pragma unroll
        for (int s = 0; s < 8; s++) { aR[s] = 0ull; aO[s] = 0ull; }

        ulonglong2 wrn = WDr[0];
        ulonglong2 won = WDo[0];
#pragma unroll 2
        for (int kk = 0; kk < 32; kk++) {
            const ulonglong2 wr = wrn, wo = won;
            const int kn = (kk < 31) ? (kk + 1) : 31;   // last: harmless reload
            wrn = WDr[kn * 64];
            won = WDo[kn * 64];
            const float* hp = s_h + pb + kk * 4;
            ulonglong2 h0 = *(const ulonglong2*)(hp);
            ulonglong2 h1 = *(const ulonglong2*)(hp + 128);
            ulonglong2 h2 = *(const ulonglong2*)(hp + 256);
            ulonglong2 h3 = *(const ulonglong2*)(hp + 384);
            ulonglong2 h4 = *(const ulonglong2*)(hp + 512);
            GEMM_STEP(0, h0)
            ulonglong2 h5 = *(const ulonglong2*)(hp + 640);
            GEMM_STEP(1, h1)
            ulonglong2 h6 = *(const ulonglong2*)(hp + 768);
            GEMM_STEP(2, h2)
            ulonglong2 h7 = *(const ulonglong2*)(hp + 896);
            GEMM_STEP(3, h3)
            GEMM_STEP(4, h4)
            GEMM_STEP(5, h5)
            GEMM_STEP(6, h6)
            GEMM_STEP(7, h7)
        }

        // hr -> smem plain layout
#pragma unroll
        for (int s = 0; s < 8; s++) {
            float2 v = upk(aR[s]);
            const int r0 = rg + 8 * s;
            s_hr[r0 * 64 + col]       = v.x;
            s_hr[(r0 + 4) * 64 + col] = v.y;
        }
        __syncthreads();

        // sparse aggregation + bias + root + relu (+ residual / final output)
        const float brel = brel_mid[L * 64 + col];
        const bool last = (L == 5);
#pragma unroll
        for (int s = 0; s < 8; s++) {
            float2 hro = upk(aO[s]);
            const int r0 = rg + 8 * s;      // always < 62
            const int r1 = r0 + 4;
            {
                float aa = brel + hro.x;
                float ab = 0.f;
                const float2* tk = s_tk + r0 * 10;
#pragma unroll
                for (int u = 0; u < 10; u += 2) {
                    float2 e0 = tk[u], e1 = tk[u + 1];
                    aa = fmaf(e0.x, s_hr[__float_as_int(e0.y) * 64 + col], aa);
                    ab = fmaf(e1.x, s_hr[__float_as_int(e1.y) * 64 + col], ab);
                }
                float v = fmaxf(aa + ab, 0.f);
                const int ha = pb + s * 128 + col * 2;
                if (last) out[base + r0 * 64 + col] = v * P0[base + r0 * 64 + col];
                else      s_h[ha] = s_h[ha] + v;
            }
            if (r1 < 62) {
                float aa = brel + hro.y;
                float ab = 0.f;
                const float2* tk = s_tk + r1 * 10;
#pragma unroll
                for (int u = 0; u < 10; u += 2) {
                    float2 e0 = tk[u], e1 = tk[u + 1];
                    aa = fmaf(e0.x, s_hr[__float_as_int(e0.y) * 64 + col], aa);
                    ab = fmaf(e1.x, s_hr[__float_as_int(e1.y) * 64 + col], ab);
                }
                float v = fmaxf(aa + ab, 0.f);
                const int ha = pb + s * 128 + col * 2 + 1;
                if (last) out[base + r1 * 64 + col] = v * P0[base + r1 * 64 + col];
                else      s_h[ha] = s_h[ha] + v;
            }
        }
        __syncthreads();
    }
}

// ============================================================================
// launch
// ============================================================================
extern "C" void kernel_launch(void* const* d_in, const int* in_sizes, int n_in,
                              void* d_out, int out_size) {
    const float* x        = (const float*)d_in[0];
    const float* gate_w   = (const float*)d_in[1];
    const float* gate_b   = (const float*)d_in[2];
    const float* bnlin_w  = (const float*)d_in[3];
    const float* bnlin_b  = (const float*)d_in[4];
    const float* rel_w1   = (const float*)d_in[5];
    const float* rel_b1   = (const float*)d_in[6];
    const float* root_w1  = (const float*)d_in[7];
    const float* rel_w_m  = (const float*)d_in[8];
    const float* rel_b_m  = (const float*)d_in[9];
    const float* root_w_m = (const float*)d_in[10];
    float* out = (float*)d_out;

    proj_kernel<<<dim3(4, 1985), 256>>>(x, gate_w, bnlin_w, rel_w1, root_w1,
                                        gate_b, bnlin_b, rel_w_m, root_w_m);
    graph_kernel<<<4096, 256>>>(rel_b_m, rel_b1, out);
}